// round 2
// baseline (speedup 1.0000x reference)
#include <cuda_runtime.h>
#include <math.h>

#define D_MODEL 1024
#define D_INNER 2048
#define D_STATE 16
#define DT_RANK 64
#define CONV_K  4
#define BSZ     2
#define SEQ     2048
#define BL      (BSZ*SEQ)            // 4096
#define XDBL_C  (DT_RANK + 2*D_STATE) // 96

// ---------------- scratch (static device globals; no dynamic alloc) ---------
__device__ float g_xn  [BL * D_MODEL];      // layernorm output
__device__ float g_xz  [BL * 2 * D_INNER];  // in-proj output (xc | z)
__device__ float g_u   [BL * D_INNER];      // conv+silu output (u)
__device__ float g_xdbl[BL * XDBL_C];       // x_proj output (dt_r | B | C)
__device__ float g_dl  [BL * D_INNER];      // delta (post softplus)
__device__ float g_y   [BL * D_INNER];      // scan output, then gated in-place

// ---------------- LayerNorm -------------------------------------------------
__global__ __launch_bounds__(256) void ln_kernel(
    const float* __restrict__ x, const float* __restrict__ g,
    const float* __restrict__ b, float* __restrict__ out)
{
    int row = blockIdx.x;
    const float4* xr = (const float4*)(x + (size_t)row * D_MODEL);
    float4 v = xr[threadIdx.x];
    float s  = v.x + v.y + v.z + v.w;
    float ss = v.x*v.x + v.y*v.y + v.z*v.z + v.w*v.w;
    #pragma unroll
    for (int o = 16; o; o >>= 1) {
        s  += __shfl_xor_sync(0xffffffffu, s, o);
        ss += __shfl_xor_sync(0xffffffffu, ss, o);
    }
    __shared__ float red[16];
    __shared__ float mu_s, rstd_s;
    int w = threadIdx.x >> 5, lane = threadIdx.x & 31;
    if (lane == 0) { red[w] = s; red[8 + w] = ss; }
    __syncthreads();
    if (threadIdx.x == 0) {
        float S = 0.f, SS = 0.f;
        #pragma unroll
        for (int i = 0; i < 8; i++) { S += red[i]; SS += red[8 + i]; }
        float mu = S * (1.f / D_MODEL);
        float var = SS * (1.f / D_MODEL) - mu * mu;
        mu_s = mu; rstd_s = rsqrtf(var + 1e-5f);
    }
    __syncthreads();
    float mu = mu_s, r = rstd_s;
    float4 gv = ((const float4*)g)[threadIdx.x];
    float4 bv = ((const float4*)b)[threadIdx.x];
    float4 o;
    o.x = (v.x - mu) * r * gv.x + bv.x;
    o.y = (v.y - mu) * r * gv.y + bv.y;
    o.z = (v.z - mu) * r * gv.z + bv.z;
    o.w = (v.w - mu) * r * gv.w + bv.w;
    ((float4*)(out + (size_t)row * D_MODEL))[threadIdx.x] = o;
}

// ---------------- generic NT GEMM: C[M,N] = A[M,K] * B[N,K]^T ---------------
// EPI: 0 = none, 1 = softplus(acc + bias[n]) (delta path), 2 = acc + res[m*ldc+n]
template<int BM, int BN, int BK, int TM, int TN, int EPI>
__global__ __launch_bounds__((BM/TM)*(BN/TN))
void gemm_nt(const float* __restrict__ A, int lda,
             const float* __restrict__ B, int ldb,
             float* __restrict__ C, int ldc,
             int M, int N, int K,
             const float* __restrict__ bias,
             const float* __restrict__ res)
{
    constexpr int NTHR = (BM/TM)*(BN/TN);
    __shared__ float As[BK][BM];
    __shared__ float Bs[BK][BN];
    int m0 = blockIdx.y * BM;
    int n0 = blockIdx.x * BN;
    int tid = threadIdx.x;
    int tx = tid % (BN/TN);
    int ty = tid / (BN/TN);

    float acc[TM][TN];
    #pragma unroll
    for (int i = 0; i < TM; i++)
        #pragma unroll
        for (int j = 0; j < TN; j++) acc[i][j] = 0.f;

    for (int k0 = 0; k0 < K; k0 += BK) {
        #pragma unroll
        for (int i = tid; i < BM*BK; i += NTHR) {
            int kk = i % BK, mm = i / BK;
            As[kk][mm] = A[(size_t)(m0 + mm) * lda + k0 + kk];
        }
        #pragma unroll
        for (int i = tid; i < BN*BK; i += NTHR) {
            int kk = i % BK, nn = i / BK;
            Bs[kk][nn] = (n0 + nn < N) ? B[(size_t)(n0 + nn) * ldb + k0 + kk] : 0.f;
        }
        __syncthreads();
        #pragma unroll
        for (int k = 0; k < BK; k++) {
            float ra[TM], rb[TN];
            #pragma unroll
            for (int i = 0; i < TM; i++) ra[i] = As[k][ty*TM + i];
            #pragma unroll
            for (int j = 0; j < TN; j++) rb[j] = Bs[k][tx*TN + j];
            #pragma unroll
            for (int i = 0; i < TM; i++)
                #pragma unroll
                for (int j = 0; j < TN; j++)
                    acc[i][j] = fmaf(ra[i], rb[j], acc[i][j]);
        }
        __syncthreads();
    }

    #pragma unroll
    for (int i = 0; i < TM; i++) {
        int m = m0 + ty*TM + i;
        #pragma unroll
        for (int j = 0; j < TN; j++) {
            int n = n0 + tx*TN + j;
            if (n < N) {
                float v = acc[i][j];
                if (EPI == 1) {
                    float t = v + bias[n];
                    float e = __expf(t);
                    v = (t > 15.f) ? t : log1pf(e);   // softplus
                } else if (EPI == 2) {
                    v += res[(size_t)m * ldc + n];
                }
                C[(size_t)m * ldc + n] = v;
            }
        }
    }
}

// ---------------- causal depthwise conv (K=4) + SiLU ------------------------
__global__ __launch_bounds__(256) void conv_silu_kernel(
    const float* __restrict__ xz, const float* __restrict__ w,
    const float* __restrict__ bias, float* __restrict__ u)
{
    int idx = blockIdx.x * 256 + threadIdx.x;
    if (idx >= BL * D_INNER) return;
    int d = idx % D_INNER;
    int t = (idx / D_INNER) % SEQ;
    int b = idx / (D_INNER * SEQ);
    float acc = bias[d];
    const float* wr = w + d * CONV_K;
    #pragma unroll
    for (int k = 0; k < CONV_K; k++) {
        int ts = t - (CONV_K - 1) + k;
        if (ts >= 0)
            acc += wr[k] * xz[(size_t)(b * SEQ + ts) * (2 * D_INNER) + d];
    }
    float sg = 1.f / (1.f + __expf(-acc));
    u[idx] = acc * sg;
}

// ---------------- selective scan --------------------------------------------
// One 16-lane group per channel d; lane n owns state n. Chunked smem staging.
#define SC_DC 32
#define SC_TC 64
__global__ __launch_bounds__(SC_DC * D_STATE) void scan_kernel(
    const float* __restrict__ u, const float* __restrict__ dl,
    const float* __restrict__ xdbl, const float* __restrict__ A_log,
    float* __restrict__ y)
{
    __shared__ float u_s [SC_TC][SC_DC];
    __shared__ float dl_s[SC_TC][SC_DC];
    __shared__ float B_s [SC_TC][D_STATE];
    __shared__ float C_s [SC_TC][D_STATE];
    __shared__ float y_s [SC_TC][SC_DC];

    int b  = blockIdx.y;
    int d0 = blockIdx.x * SC_DC;
    int tid = threadIdx.x;
    int g = tid >> 4;        // channel within block
    int n = tid & 15;        // state index
    int d = d0 + g;

    float a = -expf(A_log[d * D_STATE + n]);
    float s = 0.f;

    for (int t0 = 0; t0 < SEQ; t0 += SC_TC) {
        for (int i = tid; i < SC_TC * SC_DC; i += SC_DC * D_STATE) {
            int tt = i / SC_DC, gg = i % SC_DC;
            int gi = (b * SEQ + t0 + tt) * D_INNER + d0 + gg;
            u_s [tt][gg] = u [gi];
            dl_s[tt][gg] = dl[gi];
        }
        for (int i = tid; i < SC_TC * D_STATE; i += SC_DC * D_STATE) {
            int tt = i / D_STATE, nn = i % D_STATE;
            const float* r = xdbl + (size_t)(b * SEQ + t0 + tt) * XDBL_C + DT_RANK;
            B_s[tt][nn] = r[nn];
            C_s[tt][nn] = r[D_STATE + nn];
        }
        __syncthreads();
        #pragma unroll 4
        for (int t = 0; t < SC_TC; t++) {
            float dlt = dl_s[t][g];
            float dA  = __expf(dlt * a);
            float dbu = dlt * B_s[t][n] * u_s[t][g];
            s = fmaf(dA, s, dbu);
            float part = s * C_s[t][n];
            part += __shfl_xor_sync(0xffffffffu, part, 8);
            part += __shfl_xor_sync(0xffffffffu, part, 4);
            part += __shfl_xor_sync(0xffffffffu, part, 2);
            part += __shfl_xor_sync(0xffffffffu, part, 1);
            if (n == 0) y_s[t][g] = part;
        }
        __syncthreads();
        for (int i = tid; i < SC_TC * SC_DC; i += SC_DC * D_STATE) {
            int tt = i / SC_DC, gg = i % SC_DC;
            y[(b * SEQ + t0 + tt) * D_INNER + d0 + gg] = y_s[tt][gg];
        }
        // next chunk's compute is separated from this store by next loop's
        // __syncthreads(); loads write u_s/dl_s which compute no longer reads.
    }
}

// ---------------- gating: y = (y + u*D) * silu(z) ---------------------------
__global__ __launch_bounds__(256) void gate_kernel(
    const float* __restrict__ xz, const float* __restrict__ u,
    const float* __restrict__ Dp, float* __restrict__ y)
{
    int idx = blockIdx.x * 256 + threadIdx.x;
    if (idx >= BL * D_INNER) return;
    int d = idx % D_INNER;
    int row = idx / D_INNER;
    float z = xz[(size_t)row * (2 * D_INNER) + D_INNER + d];
    float sz = z / (1.f + __expf(-z));
    y[idx] = (y[idx] + u[idx] * Dp[d]) * sz;
}

// ---------------- launch ----------------------------------------------------
extern "C" void kernel_launch(void* const* d_in, const int* in_sizes, int n_in,
                              void* d_out, int out_size)
{
    const float* x      = (const float*)d_in[0];
    const float* ln_g   = (const float*)d_in[1];
    const float* ln_b   = (const float*)d_in[2];
    const float* W_in   = (const float*)d_in[3];
    const float* conv_w = (const float*)d_in[4];
    const float* conv_b = (const float*)d_in[5];
    const float* A_log  = (const float*)d_in[6];
    const float* D_prm  = (const float*)d_in[7];
    const float* x_proj = (const float*)d_in[8];
    const float* dt_w   = (const float*)d_in[9];
    const float* dt_b   = (const float*)d_in[10];
    const float* W_out  = (const float*)d_in[11];
    float* out = (float*)d_out;

    float *xn, *xz, *u, *xdbl, *dl, *y;
    cudaGetSymbolAddress((void**)&xn,   g_xn);
    cudaGetSymbolAddress((void**)&xz,   g_xz);
    cudaGetSymbolAddress((void**)&u,    g_u);
    cudaGetSymbolAddress((void**)&xdbl, g_xdbl);
    cudaGetSymbolAddress((void**)&dl,   g_dl);
    cudaGetSymbolAddress((void**)&y,    g_y);

    // 1. LayerNorm
    ln_kernel<<<BL, 256>>>(x, ln_g, ln_b, xn);

    // 2. xz = xn @ W_in^T  (4096 x 4096 x 1024)
    gemm_nt<128,128,8,8,8,0><<<dim3(2*D_INNER/128, BL/128), 256>>>(
        xn, D_MODEL, W_in, D_MODEL, xz, 2*D_INNER,
        BL, 2*D_INNER, D_MODEL, nullptr, nullptr);

    // 3. causal depthwise conv + SiLU -> u
    conv_silu_kernel<<<(BL*D_INNER + 255)/256, 256>>>(xz, conv_w, conv_b, u);

    // 4. x_dbl = u @ x_proj^T  (4096 x 96 x 2048)
    gemm_nt<64,128,8,4,8,0><<<dim3(1, BL/64), 256>>>(
        u, D_INNER, x_proj, D_INNER, xdbl, XDBL_C,
        BL, XDBL_C, D_INNER, nullptr, nullptr);

    // 5. delta = softplus(dt_r @ dt_w^T + dt_b)  (4096 x 2048 x 64)
    gemm_nt<128,128,8,8,8,1><<<dim3(D_INNER/128, BL/128), 256>>>(
        xdbl, XDBL_C, dt_w, DT_RANK, dl, D_INNER,
        BL, D_INNER, DT_RANK, dt_b, nullptr);

    // 6. selective scan -> y
    scan_kernel<<<dim3(D_INNER/SC_DC, BSZ), SC_DC*D_STATE>>>(u, dl, xdbl, A_log, y);

    // 7. gating: y = (y + u*D) * silu(z)
    gate_kernel<<<(BL*D_INNER + 255)/256, 256>>>(xz, u, D_prm, y);

    // 8. out = y @ W_out^T + x  (4096 x 1024 x 2048)
    gemm_nt<128,128,8,8,8,2><<<dim3(D_MODEL/128, BL/128), 256>>>(
        y, D_INNER, W_out, D_INNER, out, D_MODEL,
        BL, D_MODEL, D_INNER, nullptr, x);
}

// round 3
// speedup vs baseline: 1.5888x; 1.5888x over previous
#include <cuda_runtime.h>
#include <math.h>
#include <stdint.h>

#define D_MODEL 1024
#define D_INNER 2048
#define D_STATE 16
#define DT_RANK 64
#define CONV_K  4
#define BSZ     2
#define SEQ     2048
#define BL      (BSZ*SEQ)             // 4096
#define XDBL_C  (DT_RANK + 2*D_STATE) // 96
#define XPROJ_SPLITK 4

// ---------------- scratch (static device globals; no dynamic alloc) ---------
__device__ float g_xn  [BL * D_MODEL];
__device__ float g_xz  [BL * 2 * D_INNER];
__device__ float g_u   [BL * D_INNER];
__device__ float g_xdbl[BL * XDBL_C];
__device__ float g_part[XPROJ_SPLITK * BL * XDBL_C];
__device__ float g_dl  [BL * D_INNER];
__device__ float g_y   [BL * D_INNER];

// ---------------- LayerNorm -------------------------------------------------
__global__ __launch_bounds__(256) void ln_kernel(
    const float* __restrict__ x, const float* __restrict__ g,
    const float* __restrict__ b, float* __restrict__ out)
{
    int row = blockIdx.x;
    const float4* xr = (const float4*)(x + (size_t)row * D_MODEL);
    float4 v = xr[threadIdx.x];
    float s  = v.x + v.y + v.z + v.w;
    float ss = v.x*v.x + v.y*v.y + v.z*v.z + v.w*v.w;
    #pragma unroll
    for (int o = 16; o; o >>= 1) {
        s  += __shfl_xor_sync(0xffffffffu, s, o);
        ss += __shfl_xor_sync(0xffffffffu, ss, o);
    }
    __shared__ float red[16];
    __shared__ float mu_s, rstd_s;
    int w = threadIdx.x >> 5, lane = threadIdx.x & 31;
    if (lane == 0) { red[w] = s; red[8 + w] = ss; }
    __syncthreads();
    if (threadIdx.x == 0) {
        float S = 0.f, SS = 0.f;
        #pragma unroll
        for (int i = 0; i < 8; i++) { S += red[i]; SS += red[8 + i]; }
        float mu = S * (1.f / D_MODEL);
        float var = SS * (1.f / D_MODEL) - mu * mu;
        mu_s = mu; rstd_s = rsqrtf(var + 1e-5f);
    }
    __syncthreads();
    float mu = mu_s, r = rstd_s;
    float4 gv = ((const float4*)g)[threadIdx.x];
    float4 bv = ((const float4*)b)[threadIdx.x];
    float4 o;
    o.x = (v.x - mu) * r * gv.x + bv.x;
    o.y = (v.y - mu) * r * gv.y + bv.y;
    o.z = (v.z - mu) * r * gv.z + bv.z;
    o.w = (v.w - mu) * r * gv.w + bv.w;
    ((float4*)(out + (size_t)row * D_MODEL))[threadIdx.x] = o;
}

// ---------------- TF32x3 tensor-core GEMM -----------------------------------
// C[M,N] = A[M,K] @ B[N,K]^T      (A row-major MxK, B row-major NxK)
// CTA tile 128x128x32, 8 warps of 64x32, mma.sync m16n8k8 tf32, 3xTF32.
// EPI: 0 none, 1 softplus(acc+bias[n]), 2 acc+res[m*ldc+n]
// SPLITK>1: blockIdx.z selects K-slice; writes partial at C + z*M*ldc.

__device__ __forceinline__ void cp16(float* dst_smem, const float* src, int sz) {
    uint32_t d = (uint32_t)__cvta_generic_to_shared(dst_smem);
    asm volatile("cp.async.cg.shared.global [%0], [%1], 16, %2;\n"
                 :: "r"(d), "l"(src), "r"(sz));
}
__device__ __forceinline__ void cp_commit() {
    asm volatile("cp.async.commit_group;\n");
}
template<int N_> __device__ __forceinline__ void cp_wait() {
    asm volatile("cp.async.wait_group %0;\n" :: "n"(N_));
}

__device__ __forceinline__ void split_tf32(float x, uint32_t& hi, uint32_t& lo) {
    uint32_t h;
    asm("cvt.rna.tf32.f32 %0, %1;\n" : "=r"(h) : "f"(x));
    hi = h;
    lo = __float_as_uint(x - __uint_as_float(h));
}

__device__ __forceinline__ void mma8(float* c, const uint32_t* a, const uint32_t* b) {
    asm volatile(
        "mma.sync.aligned.m16n8k8.row.col.f32.tf32.tf32.f32 "
        "{%0,%1,%2,%3}, {%4,%5,%6,%7}, {%8,%9}, {%0,%1,%2,%3};\n"
        : "+f"(c[0]), "+f"(c[1]), "+f"(c[2]), "+f"(c[3])
        : "r"(a[0]), "r"(a[1]), "r"(a[2]), "r"(a[3]), "r"(b[0]), "r"(b[1]));
}

#define GT_STAGES 3
#define GT_STAGE_FLOATS 8192   // A 128*32 + B 128*32
#define GT_SMEM_BYTES (GT_STAGES * GT_STAGE_FLOATS * 4)

template<int EPI, int SPLITK>
__global__ __launch_bounds__(256, 1) void gemm_tc(
    const float* __restrict__ A, int lda,
    const float* __restrict__ B, int ldb,
    float* __restrict__ C, int ldc,
    int M, int N, int K,
    const float* __restrict__ bias,
    const float* __restrict__ res)
{
    extern __shared__ float sm[];
    int tid = threadIdx.x;
    int m0 = blockIdx.y * 128;
    int n0 = blockIdx.x * 128;

    if (SPLITK > 1) {
        int z = blockIdx.z;
        int Ks = K / SPLITK;
        A += (size_t)z * Ks;
        B += (size_t)z * Ks;
        C += (size_t)z * M * ldc;
        K = Ks;
    }

    int pm = tid & 127;              // producer row within tile
    int pk = (tid >> 7) * 16;        // producer k base (0 or 16)
    const float* Asrc = A + (size_t)(m0 + pm) * lda + pk;
    const float* Bsrc;
    int bsz;
    {
        int n = n0 + pm;
        bsz = (n < N) ? 16 : 0;
        Bsrc = B + (size_t)(bsz ? n : 0) * ldb + pk;
    }
    int psw_m = (pm & 7) << 2;       // XOR swizzle for this producer row

    int lane = tid & 31, wid = tid >> 5;
    int p = lane >> 2, q = lane & 3;
    int wm = (wid >> 2) * 64;        // warp m offset
    int wn = (wid & 3) * 32;         // warp n offset

    float acc[4][4][4];
    #pragma unroll
    for (int i = 0; i < 4; i++)
        #pragma unroll
        for (int j = 0; j < 4; j++)
            #pragma unroll
            for (int r = 0; r < 4; r++) acc[i][j][r] = 0.f;

    int KT = K / 32;

    // prologue: fill stages 0..GT_STAGES-2
    #pragma unroll
    for (int s = 0; s < GT_STAGES - 1; s++) {
        float* As = sm + s * GT_STAGE_FLOATS;
        float* Bs = As + 4096;
        int kb = s * 32;
        float* ad = As + pm * 32;
        float* bd = Bs + pm * 32;
        #pragma unroll
        for (int j = 0; j < 4; j++) {
            int k0 = pk + j * 4;
            cp16(ad + (k0 ^ psw_m), Asrc + kb + j * 4, 16);
            cp16(bd + (k0 ^ psw_m), Bsrc + kb + j * 4, bsz);
        }
        cp_commit();
    }

    for (int kt = 0; kt < KT; kt++) {
        cp_wait<GT_STAGES - 2>();
        __syncthreads();

        // prefetch stage kt + GT_STAGES - 1
        {
            int kf = kt + GT_STAGES - 1;
            if (kf < KT) {
                int s = kf % GT_STAGES;
                float* As = sm + s * GT_STAGE_FLOATS;
                float* Bs = As + 4096;
                int kb = kf * 32;
                float* ad = As + pm * 32;
                float* bd = Bs + pm * 32;
                #pragma unroll
                for (int j = 0; j < 4; j++) {
                    int k0 = pk + j * 4;
                    cp16(ad + (k0 ^ psw_m), Asrc + kb + j * 4, 16);
                    cp16(bd + (k0 ^ psw_m), Bsrc + kb + j * 4, bsz);
                }
            }
            cp_commit();
        }

        // compute stage kt % GT_STAGES
        const float* As = sm + (kt % GT_STAGES) * GT_STAGE_FLOATS;
        const float* Bs = As + 4096;
        #pragma unroll
        for (int ks8 = 0; ks8 < 4; ks8++) {
            int ks = ks8 * 8;
            uint32_t ahi[4][4], alo[4][4], bhi[4][2], blo[4][2];
            #pragma unroll
            for (int mi = 0; mi < 4; mi++) {
                int row = wm + mi * 16 + p;
                const float* ar = As + row * 32;
                int sw = (row & 7) << 2;
                int i0 = (ks + q) ^ sw;
                int i1 = (ks + 4 + q) ^ sw;
                split_tf32(ar[i0],        ahi[mi][0], alo[mi][0]);
                split_tf32(ar[256 + i0],  ahi[mi][1], alo[mi][1]);
                split_tf32(ar[i1],        ahi[mi][2], alo[mi][2]);
                split_tf32(ar[256 + i1],  ahi[mi][3], alo[mi][3]);
            }
            #pragma unroll
            for (int ni = 0; ni < 4; ni++) {
                int col = wn + ni * 8 + p;
                const float* br = Bs + col * 32;
                int sw = (col & 7) << 2;
                split_tf32(br[(ks + q) ^ sw],     bhi[ni][0], blo[ni][0]);
                split_tf32(br[(ks + 4 + q) ^ sw], bhi[ni][1], blo[ni][1]);
            }
            #pragma unroll
            for (int mi = 0; mi < 4; mi++)
                #pragma unroll
                for (int ni = 0; ni < 4; ni++) {
                    mma8(acc[mi][ni], ahi[mi], bhi[ni]);
                    mma8(acc[mi][ni], ahi[mi], blo[ni]);
                    mma8(acc[mi][ni], alo[mi], bhi[ni]);
                }
        }
        __syncthreads();
    }

    // epilogue
    #pragma unroll
    for (int mi = 0; mi < 4; mi++) {
        int row = m0 + wm + mi * 16 + p;
        #pragma unroll
        for (int ni = 0; ni < 4; ni++) {
            int col = n0 + wn + ni * 8 + q * 2;
            if (col < N) {
                float v[4] = { acc[mi][ni][0], acc[mi][ni][1],
                               acc[mi][ni][2], acc[mi][ni][3] };
                if (EPI == 1) {
                    #pragma unroll
                    for (int r = 0; r < 4; r++) {
                        float t = v[r] + bias[col + (r & 1)];
                        float e = __expf(t);
                        v[r] = (t > 15.f) ? t : log1pf(e);
                    }
                } else if (EPI == 2) {
                    v[0] += res[(size_t)row * ldc + col];
                    v[1] += res[(size_t)row * ldc + col + 1];
                    v[2] += res[(size_t)(row + 8) * ldc + col];
                    v[3] += res[(size_t)(row + 8) * ldc + col + 1];
                }
                float* c0 = C + (size_t)row * ldc + col;
                float* c1 = C + (size_t)(row + 8) * ldc + col;
                c0[0] = v[0]; c0[1] = v[1];
                c1[0] = v[2]; c1[1] = v[3];
            }
        }
    }
}

// ---------------- split-K reduce for x_proj ---------------------------------
__global__ __launch_bounds__(256) void xproj_reduce(
    const float* __restrict__ part, float* __restrict__ out)
{
    int i = blockIdx.x * 256 + threadIdx.x;
    if (i >= BL * XDBL_C) return;
    const int stride = BL * XDBL_C;
    float s = part[i];
    #pragma unroll
    for (int z = 1; z < XPROJ_SPLITK; z++) s += part[i + z * stride];
    out[i] = s;
}

// ---------------- causal depthwise conv (K=4) + SiLU ------------------------
__global__ __launch_bounds__(256) void conv_silu_kernel(
    const float* __restrict__ xz, const float* __restrict__ w,
    const float* __restrict__ bias, float* __restrict__ u)
{
    int idx = blockIdx.x * 256 + threadIdx.x;
    if (idx >= BL * D_INNER) return;
    int d = idx % D_INNER;
    int t = (idx / D_INNER) % SEQ;
    int b = idx / (D_INNER * SEQ);
    float acc = bias[d];
    const float* wr = w + d * CONV_K;
    #pragma unroll
    for (int k = 0; k < CONV_K; k++) {
        int ts = t - (CONV_K - 1) + k;
        if (ts >= 0)
            acc += wr[k] * xz[(size_t)(b * SEQ + ts) * (2 * D_INNER) + d];
    }
    float sg = 1.f / (1.f + __expf(-acc));
    u[idx] = acc * sg;
}

// ---------------- selective scan (gate fused into store) --------------------
#define SC_DC 32
#define SC_TC 64
__global__ __launch_bounds__(SC_DC * D_STATE) void scan_kernel(
    const float* __restrict__ u, const float* __restrict__ dl,
    const float* __restrict__ xdbl, const float* __restrict__ A_log,
    const float* __restrict__ xz, const float* __restrict__ Dp,
    float* __restrict__ y)
{
    __shared__ float u_s [SC_TC][SC_DC];
    __shared__ float dl_s[SC_TC][SC_DC];
    __shared__ float B_s [SC_TC][D_STATE];
    __shared__ float C_s [SC_TC][D_STATE];
    __shared__ float y_s [SC_TC][SC_DC];

    int b  = blockIdx.y;
    int d0 = blockIdx.x * SC_DC;
    int tid = threadIdx.x;
    int g = tid >> 4;
    int n = tid & 15;
    int d = d0 + g;

    float a = -expf(A_log[d * D_STATE + n]);
    float s = 0.f;

    for (int t0 = 0; t0 < SEQ; t0 += SC_TC) {
        for (int i = tid; i < SC_TC * SC_DC; i += SC_DC * D_STATE) {
            int tt = i / SC_DC, gg = i % SC_DC;
            int gi = (b * SEQ + t0 + tt) * D_INNER + d0 + gg;
            u_s [tt][gg] = u [gi];
            dl_s[tt][gg] = dl[gi];
        }
        for (int i = tid; i < SC_TC * D_STATE; i += SC_DC * D_STATE) {
            int tt = i / D_STATE, nn = i % D_STATE;
            const float* r = xdbl + (size_t)(b * SEQ + t0 + tt) * XDBL_C + DT_RANK;
            B_s[tt][nn] = r[nn];
            C_s[tt][nn] = r[D_STATE + nn];
        }
        __syncthreads();
        #pragma unroll 4
        for (int t = 0; t < SC_TC; t++) {
            float dlt = dl_s[t][g];
            float dA  = __expf(dlt * a);
            float dbu = dlt * B_s[t][n] * u_s[t][g];
            s = fmaf(dA, s, dbu);
            float part = s * C_s[t][n];
            part += __shfl_xor_sync(0xffffffffu, part, 8);
            part += __shfl_xor_sync(0xffffffffu, part, 4);
            part += __shfl_xor_sync(0xffffffffu, part, 2);
            part += __shfl_xor_sync(0xffffffffu, part, 1);
            if (n == 0) y_s[t][g] = part;
        }
        __syncthreads();
        // fused gate: y = (scan_y + u*D) * silu(z)
        for (int i = tid; i < SC_TC * SC_DC; i += SC_DC * D_STATE) {
            int tt = i / SC_DC, gg = i % SC_DC;
            int rowg = b * SEQ + t0 + tt;
            float z = xz[(size_t)rowg * (2 * D_INNER) + D_INNER + d0 + gg];
            float sz = z / (1.f + __expf(-z));
            float val = (y_s[tt][gg] + u_s[tt][gg] * Dp[d0 + gg]) * sz;
            y[(size_t)rowg * D_INNER + d0 + gg] = val;
        }
        __syncthreads();
    }
}

// ---------------- launch ----------------------------------------------------
extern "C" void kernel_launch(void* const* d_in, const int* in_sizes, int n_in,
                              void* d_out, int out_size)
{
    const float* x      = (const float*)d_in[0];
    const float* ln_g   = (const float*)d_in[1];
    const float* ln_b   = (const float*)d_in[2];
    const float* W_in   = (const float*)d_in[3];
    const float* conv_w = (const float*)d_in[4];
    const float* conv_b = (const float*)d_in[5];
    const float* A_log  = (const float*)d_in[6];
    const float* D_prm  = (const float*)d_in[7];
    const float* x_proj = (const float*)d_in[8];
    const float* dt_w   = (const float*)d_in[9];
    const float* dt_b   = (const float*)d_in[10];
    const float* W_out  = (const float*)d_in[11];
    float* out = (float*)d_out;

    float *xn, *xz, *u, *xdbl, *part, *dl, *y;
    cudaGetSymbolAddress((void**)&xn,   g_xn);
    cudaGetSymbolAddress((void**)&xz,   g_xz);
    cudaGetSymbolAddress((void**)&u,    g_u);
    cudaGetSymbolAddress((void**)&xdbl, g_xdbl);
    cudaGetSymbolAddress((void**)&part, g_part);
    cudaGetSymbolAddress((void**)&dl,   g_dl);
    cudaGetSymbolAddress((void**)&y,    g_y);

    cudaFuncSetAttribute(gemm_tc<0,1>, cudaFuncAttributeMaxDynamicSharedMemorySize, GT_SMEM_BYTES);
    cudaFuncSetAttribute(gemm_tc<0,XPROJ_SPLITK>, cudaFuncAttributeMaxDynamicSharedMemorySize, GT_SMEM_BYTES);
    cudaFuncSetAttribute(gemm_tc<1,1>, cudaFuncAttributeMaxDynamicSharedMemorySize, GT_SMEM_BYTES);
    cudaFuncSetAttribute(gemm_tc<2,1>, cudaFuncAttributeMaxDynamicSharedMemorySize, GT_SMEM_BYTES);

    // 1. LayerNorm
    ln_kernel<<<BL, 256>>>(x, ln_g, ln_b, xn);

    // 2. xz = xn @ W_in^T   (4096 x 4096 x 1024)
    gemm_tc<0,1><<<dim3(2*D_INNER/128, BL/128), 256, GT_SMEM_BYTES>>>(
        xn, D_MODEL, W_in, D_MODEL, xz, 2*D_INNER,
        BL, 2*D_INNER, D_MODEL, nullptr, nullptr);

    // 3. causal depthwise conv + SiLU -> u
    conv_silu_kernel<<<(BL*D_INNER + 255)/256, 256>>>(xz, conv_w, conv_b, u);

    // 4. x_dbl = u @ x_proj^T  (4096 x 96 x 2048), split-K=4 -> partials
    gemm_tc<0,XPROJ_SPLITK><<<dim3(1, BL/128, XPROJ_SPLITK), 256, GT_SMEM_BYTES>>>(
        u, D_INNER, x_proj, D_INNER, part, XDBL_C,
        BL, XDBL_C, D_INNER, nullptr, nullptr);
    xproj_reduce<<<(BL*XDBL_C + 255)/256, 256>>>(part, xdbl);

    // 5. delta = softplus(dt_r @ dt_w^T + dt_b)  (4096 x 2048 x 64)
    gemm_tc<1,1><<<dim3(D_INNER/128, BL/128), 256, GT_SMEM_BYTES>>>(
        xdbl, XDBL_C, dt_w, DT_RANK, dl, D_INNER,
        BL, D_INNER, DT_RANK, dt_b, nullptr);

    // 6. selective scan + fused gate -> y
    scan_kernel<<<dim3(D_INNER/SC_DC, BSZ), SC_DC*D_STATE>>>(
        u, dl, xdbl, A_log, xz, D_prm, y);

    // 7. out = y @ W_out^T + x  (4096 x 1024 x 2048)
    gemm_tc<2,1><<<dim3(D_MODEL/128, BL/128), 256, GT_SMEM_BYTES>>>(
        y, D_INNER, W_out, D_INNER, out, D_MODEL,
        BL, D_MODEL, D_INNER, nullptr, x);
}

// round 5
// speedup vs baseline: 2.0501x; 1.2903x over previous
#include <cuda_runtime.h>
#include <cuda_fp16.h>
#include <math.h>
#include <stdint.h>

#define D_MODEL 1024
#define D_INNER 2048
#define D_STATE 16
#define DT_RANK 64
#define CONV_K  4
#define BSZ     2
#define SEQ     2048
#define BL      (BSZ*SEQ)             // 4096
#define XDBL_C  (DT_RANK + 2*D_STATE) // 96
#define XPROJ_SPLITK 4

// ---------------- scratch (static device globals) ---------------------------
__device__ __align__(16) __half g_xn_hi[BL * D_MODEL];
__device__ __align__(16) __half g_xn_lo[BL * D_MODEL];
__device__ __align__(16) float  g_xz   [BL * 2 * D_INNER];
__device__ __align__(16) float  g_u    [BL * D_INNER];
__device__ __align__(16) __half g_u_hi [BL * D_INNER];
__device__ __align__(16) __half g_u_lo [BL * D_INNER];
__device__ __align__(16) float  g_xdbl [BL * XDBL_C];
__device__ __align__(16) __half g_xd_hi[BL * XDBL_C];
__device__ __align__(16) __half g_xd_lo[BL * XDBL_C];
__device__ __align__(16) float  g_part [XPROJ_SPLITK * BL * XDBL_C];
__device__ __align__(16) float  g_dl   [BL * D_INNER];
__device__ __align__(16) __half g_y_hi [BL * D_INNER];
__device__ __align__(16) __half g_y_lo [BL * D_INNER];
__device__ __align__(16) __half g_wi_hi[2 * D_INNER * D_MODEL];
__device__ __align__(16) __half g_wi_lo[2 * D_INNER * D_MODEL];
__device__ __align__(16) __half g_xp_hi[XDBL_C * D_INNER];
__device__ __align__(16) __half g_xp_lo[XDBL_C * D_INNER];
__device__ __align__(16) __half g_dw_hi[D_INNER * DT_RANK];
__device__ __align__(16) __half g_dw_lo[D_INNER * DT_RANK];
__device__ __align__(16) __half g_wo_hi[D_MODEL * D_INNER];
__device__ __align__(16) __half g_wo_lo[D_MODEL * D_INNER];

// ---------------- helpers ----------------------------------------------------
__device__ __forceinline__ void cp16(void* dst_smem, const void* src, int sz) {
    uint32_t d = (uint32_t)__cvta_generic_to_shared(dst_smem);
    asm volatile("cp.async.cg.shared.global [%0], [%1], 16, %2;\n"
                 :: "r"(d), "l"(src), "r"(sz));
}
__device__ __forceinline__ void cp_commit() {
    asm volatile("cp.async.commit_group;\n");
}
template<int N_> __device__ __forceinline__ void cp_wait() {
    asm volatile("cp.async.wait_group %0;\n" :: "n"(N_));
}
__device__ __forceinline__ void h_split(float x, __half& h, __half& l) {
    h = __float2half_rn(x);
    l = __float2half_rn(x - __half2float(h));
}
__device__ __forceinline__ void mma_f16(float* c, uint32_t a0, uint32_t a1, uint32_t b0) {
    asm volatile(
        "mma.sync.aligned.m16n8k8.row.col.f32.f16.f16.f32 "
        "{%0,%1,%2,%3}, {%4,%5}, {%6}, {%0,%1,%2,%3};\n"
        : "+f"(c[0]), "+f"(c[1]), "+f"(c[2]), "+f"(c[3])
        : "r"(a0), "r"(a1), "r"(b0));
}

// ---------------- FP16x3 tensor-core GEMM ------------------------------------
// C[M,N] = (Ahi+Alo)[M,K] @ ((Bhi+Blo)[N,K])^T   (3-term compensated)
// CTA tile 128x128, K chunk 32. 8 warps: warp tile 32x64 (wm=(wid&3)*32, wn=(wid>>2)*64)
// smem: 2 stages x 4 tiles (Ahi,Alo,Bhi,Blo), each 128 rows x 20 words (16 data + 4 pad)
// EPI: 0 none, 1 softplus(acc+bias[n]), 2 acc+res[m*ldc+n]
#define RSTRIDE 20
#define TILE_W  (128 * RSTRIDE)   // 2560 words
#define STAGE_W (4 * TILE_W)      // 10240 words = 40KB
#define G5_SMEM (2 * STAGE_W * 4) // 81920 bytes

template<int EPI, int SPLITK>
__global__ __launch_bounds__(256, 2) void gemm_f16x3(
    const __half* __restrict__ Ahi, const __half* __restrict__ Alo, int lda,
    const __half* __restrict__ Bhi, const __half* __restrict__ Blo, int ldb,
    float* __restrict__ C, int ldc, int M, int N, int K,
    const float* __restrict__ bias, const float* __restrict__ res)
{
    extern __shared__ uint32_t sm[];
    int tid = threadIdx.x;
    int m0 = blockIdx.y * 128;
    int n0 = blockIdx.x * 128;

    if (SPLITK > 1) {
        int z = blockIdx.z;
        int Ks = K / SPLITK;
        Ahi += (size_t)z * Ks; Alo += (size_t)z * Ks;
        Bhi += (size_t)z * Ks; Blo += (size_t)z * Ks;
        C += (size_t)z * M * ldc;
        K = Ks;
    }
    int KT = K / 32;

    int lane = tid & 31, wid = tid >> 5;
    int p = lane >> 2, q = lane & 3;
    int wm = (wid & 3) * 32;
    int wn = (wid >> 2) * 64;

    float acc[2][8][4];
    #pragma unroll
    for (int i = 0; i < 2; i++)
        #pragma unroll
        for (int j = 0; j < 8; j++)
            #pragma unroll
            for (int r = 0; r < 4; r++) acc[i][j][r] = 0.f;

    auto load_stage = [&](int kt, int slot) {
        uint32_t* base = sm + slot * STAGE_W;
        int k0 = kt * 32;
        #pragma unroll
        for (int c = tid; c < 2048; c += 256) {
            int tile = c >> 9;            // 0:Ahi 1:Alo 2:Bhi 3:Blo
            int r = (c & 511) >> 2;
            int j = c & 3;
            uint32_t* dst = base + tile * TILE_W + r * RSTRIDE + j * 4;
            if (tile < 2) {
                const __half* src = (tile == 0 ? Ahi : Alo)
                                  + (size_t)(m0 + r) * lda + k0 + j * 8;
                cp16(dst, src, 16);
            } else {
                int n = n0 + r;
                int sz = (n < N) ? 16 : 0;
                int rr = sz ? n : 0;
                const __half* src = (tile == 2 ? Bhi : Blo)
                                  + (size_t)rr * ldb + k0 + j * 8;
                cp16(dst, src, sz);
            }
        }
    };

    load_stage(0, 0); cp_commit();
    if (KT > 1) load_stage(1, 1);
    cp_commit();

    for (int kt = 0; kt < KT; kt++) {
        int slot = kt & 1;
        cp_wait<1>();
        __syncthreads();

        const uint32_t* Ah = sm + slot * STAGE_W;
        const uint32_t* Al = Ah + TILE_W;
        const uint32_t* Bh = Al + TILE_W;
        const uint32_t* Bl = Bh + TILE_W;

        #pragma unroll
        for (int ks8 = 0; ks8 < 4; ks8++) {
            int wb = ks8 * 4 + q;
            uint32_t ah[2][2], al[2][2], bh[8], bl[8];
            #pragma unroll
            for (int mi = 0; mi < 2; mi++) {
                int row = wm + mi * 16 + p;
                ah[mi][0] = Ah[row * RSTRIDE + wb];
                ah[mi][1] = Ah[(row + 8) * RSTRIDE + wb];
                al[mi][0] = Al[row * RSTRIDE + wb];
                al[mi][1] = Al[(row + 8) * RSTRIDE + wb];
            }
            #pragma unroll
            for (int ni = 0; ni < 8; ni++) {
                int col = wn + ni * 8 + p;
                bh[ni] = Bh[col * RSTRIDE + wb];
                bl[ni] = Bl[col * RSTRIDE + wb];
            }
            #pragma unroll
            for (int mi = 0; mi < 2; mi++)
                #pragma unroll
                for (int ni = 0; ni < 8; ni++) {
                    mma_f16(acc[mi][ni], ah[mi][0], ah[mi][1], bh[ni]);
                    mma_f16(acc[mi][ni], al[mi][0], al[mi][1], bh[ni]);
                    mma_f16(acc[mi][ni], ah[mi][0], ah[mi][1], bl[ni]);
                }
        }
        __syncthreads();
        if (kt + 2 < KT) load_stage(kt + 2, slot);
        cp_commit();
    }

    // epilogue
    #pragma unroll
    for (int mi = 0; mi < 2; mi++) {
        int row = m0 + wm + mi * 16 + p;
        #pragma unroll
        for (int ni = 0; ni < 8; ni++) {
            int col = n0 + wn + ni * 8 + q * 2;
            if (col < N) {
                float v[4] = { acc[mi][ni][0], acc[mi][ni][1],
                               acc[mi][ni][2], acc[mi][ni][3] };
                if (EPI == 1) {
                    #pragma unroll
                    for (int r = 0; r < 4; r++) {
                        float t = v[r] + bias[col + (r & 1)];
                        float e = __expf(t);
                        v[r] = (t > 15.f) ? t : log1pf(e);
                    }
                } else if (EPI == 2) {
                    v[0] += res[(size_t)row * ldc + col];
                    v[1] += res[(size_t)row * ldc + col + 1];
                    v[2] += res[(size_t)(row + 8) * ldc + col];
                    v[3] += res[(size_t)(row + 8) * ldc + col + 1];
                }
                float* c0 = C + (size_t)row * ldc + col;
                float* c1 = C + (size_t)(row + 8) * ldc + col;
                c0[0] = v[0]; c0[1] = v[1];
                c1[0] = v[2]; c1[1] = v[3];
            }
        }
    }
}

// ---------------- weight hi/lo split -----------------------------------------
__global__ __launch_bounds__(256) void split_kernel(
    const float* __restrict__ src, __half* __restrict__ hi,
    __half* __restrict__ lo, int n)
{
    int i = blockIdx.x * 256 + threadIdx.x;
    if (i >= n) return;
    __half h, l;
    h_split(src[i], h, l);
    hi[i] = h; lo[i] = l;
}

// ---------------- LayerNorm (writes half hi/lo) ------------------------------
__global__ __launch_bounds__(256) void ln_kernel(
    const float* __restrict__ x, const float* __restrict__ g,
    const float* __restrict__ b, __half* __restrict__ ohi, __half* __restrict__ olo)
{
    int row = blockIdx.x;
    const float4* xr = (const float4*)(x + (size_t)row * D_MODEL);
    float4 v = xr[threadIdx.x];
    float s  = v.x + v.y + v.z + v.w;
    float ss = v.x*v.x + v.y*v.y + v.z*v.z + v.w*v.w;
    #pragma unroll
    for (int o = 16; o; o >>= 1) {
        s  += __shfl_xor_sync(0xffffffffu, s, o);
        ss += __shfl_xor_sync(0xffffffffu, ss, o);
    }
    __shared__ float red[16];
    __shared__ float mu_s, rstd_s;
    int w = threadIdx.x >> 5, lane = threadIdx.x & 31;
    if (lane == 0) { red[w] = s; red[8 + w] = ss; }
    __syncthreads();
    if (threadIdx.x == 0) {
        float S = 0.f, SS = 0.f;
        #pragma unroll
        for (int i = 0; i < 8; i++) { S += red[i]; SS += red[8 + i]; }
        float mu = S * (1.f / D_MODEL);
        float var = SS * (1.f / D_MODEL) - mu * mu;
        mu_s = mu; rstd_s = rsqrtf(var + 1e-5f);
    }
    __syncthreads();
    float mu = mu_s, r = rstd_s;
    float4 gv = ((const float4*)g)[threadIdx.x];
    float4 bv = ((const float4*)b)[threadIdx.x];
    float o0 = (v.x - mu) * r * gv.x + bv.x;
    float o1 = (v.y - mu) * r * gv.y + bv.y;
    float o2 = (v.z - mu) * r * gv.z + bv.z;
    float o3 = (v.w - mu) * r * gv.w + bv.w;
    __half h0, l0, h1, l1, h2, l2, h3, l3;
    h_split(o0, h0, l0); h_split(o1, h1, l1);
    h_split(o2, h2, l2); h_split(o3, h3, l3);
    __half2* ph = (__half2*)(ohi + (size_t)row * D_MODEL);
    __half2* pl = (__half2*)(olo + (size_t)row * D_MODEL);
    ph[2*threadIdx.x]   = __halves2half2(h0, h1);
    ph[2*threadIdx.x+1] = __halves2half2(h2, h3);
    pl[2*threadIdx.x]   = __halves2half2(l0, l1);
    pl[2*threadIdx.x+1] = __halves2half2(l2, l3);
}

// ---------------- split-K reduce for x_proj -----------------------------------
__global__ __launch_bounds__(256) void xproj_reduce(
    const float* __restrict__ part, float* __restrict__ out,
    __half* __restrict__ ohi, __half* __restrict__ olo)
{
    int i = blockIdx.x * 256 + threadIdx.x;
    if (i >= BL * XDBL_C) return;
    const int stride = BL * XDBL_C;
    float s = part[i];
    #pragma unroll
    for (int z = 1; z < XPROJ_SPLITK; z++) s += part[i + z * stride];
    out[i] = s;
    __half h, l;
    h_split(s, h, l);
    ohi[i] = h; olo[i] = l;
}

// ---------------- causal depthwise conv (K=4) + SiLU --------------------------
__global__ __launch_bounds__(256) void conv_silu_kernel(
    const float* __restrict__ xz, const float* __restrict__ w,
    const float* __restrict__ bias, float* __restrict__ u,
    __half* __restrict__ uhi, __half* __restrict__ ulo)
{
    int idx = blockIdx.x * 256 + threadIdx.x;
    if (idx >= BL * D_INNER) return;
    int d = idx % D_INNER;
    int t = (idx / D_INNER) % SEQ;
    int b = idx / (D_INNER * SEQ);
    float acc = bias[d];
    const float* wr = w + d * CONV_K;
    #pragma unroll
    for (int k = 0; k < CONV_K; k++) {
        int ts = t - (CONV_K - 1) + k;
        if (ts >= 0)
            acc += wr[k] * xz[(size_t)(b * SEQ + ts) * (2 * D_INNER) + d];
    }
    float sg = 1.f / (1.f + __expf(-acc));
    float val = acc * sg;
    u[idx] = val;
    __half h, l;
    h_split(val, h, l);
    uhi[idx] = h; ulo[idx] = l;
}

// ---------------- selective scan (gate fused; writes half hi/lo) --------------
#define SC_DC 32
#define SC_TC 64
__global__ __launch_bounds__(SC_DC * D_STATE) void scan_kernel(
    const float* __restrict__ u, const float* __restrict__ dl,
    const float* __restrict__ xdbl, const float* __restrict__ A_log,
    const float* __restrict__ xz, const float* __restrict__ Dp,
    __half* __restrict__ yhi, __half* __restrict__ ylo)
{
    __shared__ float u_s [SC_TC][SC_DC];
    __shared__ float dl_s[SC_TC][SC_DC];
    __shared__ float B_s [SC_TC][D_STATE];
    __shared__ float C_s [SC_TC][D_STATE];
    __shared__ float y_s [SC_TC][SC_DC];

    int b  = blockIdx.y;
    int d0 = blockIdx.x * SC_DC;
    int tid = threadIdx.x;
    int g = tid >> 4;
    int n = tid & 15;
    int d = d0 + g;

    float a = -expf(A_log[d * D_STATE + n]);
    float s = 0.f;

    for (int t0 = 0; t0 < SEQ; t0 += SC_TC) {
        for (int i = tid; i < SC_TC * SC_DC; i += SC_DC * D_STATE) {
            int tt = i / SC_DC, gg = i % SC_DC;
            int gi = (b * SEQ + t0 + tt) * D_INNER + d0 + gg;
            u_s [tt][gg] = u [gi];
            dl_s[tt][gg] = dl[gi];
        }
        for (int i = tid; i < SC_TC * D_STATE; i += SC_DC * D_STATE) {
            int tt = i / D_STATE, nn = i % D_STATE;
            const float* r = xdbl + (size_t)(b * SEQ + t0 + tt) * XDBL_C + DT_RANK;
            B_s[tt][nn] = r[nn];
            C_s[tt][nn] = r[D_STATE + nn];
        }
        __syncthreads();
        #pragma unroll 4
        for (int t = 0; t < SC_TC; t++) {
            float dlt = dl_s[t][g];
            float dA  = __expf(dlt * a);
            float dbu = dlt * B_s[t][n] * u_s[t][g];
            s = fmaf(dA, s, dbu);
            float part = s * C_s[t][n];
            part += __shfl_xor_sync(0xffffffffu, part, 8);
            part += __shfl_xor_sync(0xffffffffu, part, 4);
            part += __shfl_xor_sync(0xffffffffu, part, 2);
            part += __shfl_xor_sync(0xffffffffu, part, 1);
            if (n == 0) y_s[t][g] = part;
        }
        __syncthreads();
        for (int i = tid; i < SC_TC * SC_DC; i += SC_DC * D_STATE) {
            int tt = i / SC_DC, gg = i % SC_DC;
            int rowg = b * SEQ + t0 + tt;
            float z = xz[(size_t)rowg * (2 * D_INNER) + D_INNER + d0 + gg];
            float sz = z / (1.f + __expf(-z));
            float val = (y_s[tt][gg] + u_s[tt][gg] * Dp[d0 + gg]) * sz;
            __half h, l;
            h_split(val, h, l);
            size_t oi = (size_t)rowg * D_INNER + d0 + gg;
            yhi[oi] = h; ylo[oi] = l;
        }
        __syncthreads();
    }
}

// ---------------- launch ------------------------------------------------------
extern "C" void kernel_launch(void* const* d_in, const int* in_sizes, int n_in,
                              void* d_out, int out_size)
{
    const float* x      = (const float*)d_in[0];
    const float* ln_g   = (const float*)d_in[1];
    const float* ln_b   = (const float*)d_in[2];
    const float* W_in   = (const float*)d_in[3];
    const float* conv_w = (const float*)d_in[4];
    const float* conv_b = (const float*)d_in[5];
    const float* A_log  = (const float*)d_in[6];
    const float* D_prm  = (const float*)d_in[7];
    const float* x_proj = (const float*)d_in[8];
    const float* dt_w   = (const float*)d_in[9];
    const float* dt_b   = (const float*)d_in[10];
    const float* W_out  = (const float*)d_in[11];
    float* out = (float*)d_out;

    __half *xn_hi, *xn_lo, *u_hi, *u_lo, *xd_hi, *xd_lo, *y_hi, *y_lo;
    __half *wi_hi, *wi_lo, *xp_hi, *xp_lo, *dw_hi, *dw_lo, *wo_hi, *wo_lo;
    float *xz, *u, *xdbl, *part, *dl;
    cudaGetSymbolAddress((void**)&xn_hi, g_xn_hi);
    cudaGetSymbolAddress((void**)&xn_lo, g_xn_lo);
    cudaGetSymbolAddress((void**)&xz,    g_xz);
    cudaGetSymbolAddress((void**)&u,     g_u);
    cudaGetSymbolAddress((void**)&u_hi,  g_u_hi);
    cudaGetSymbolAddress((void**)&u_lo,  g_u_lo);
    cudaGetSymbolAddress((void**)&xdbl,  g_xdbl);
    cudaGetSymbolAddress((void**)&xd_hi, g_xd_hi);
    cudaGetSymbolAddress((void**)&xd_lo, g_xd_lo);
    cudaGetSymbolAddress((void**)&part,  g_part);
    cudaGetSymbolAddress((void**)&dl,    g_dl);
    cudaGetSymbolAddress((void**)&y_hi,  g_y_hi);
    cudaGetSymbolAddress((void**)&y_lo,  g_y_lo);
    cudaGetSymbolAddress((void**)&wi_hi, g_wi_hi);
    cudaGetSymbolAddress((void**)&wi_lo, g_wi_lo);
    cudaGetSymbolAddress((void**)&xp_hi, g_xp_hi);
    cudaGetSymbolAddress((void**)&xp_lo, g_xp_lo);
    cudaGetSymbolAddress((void**)&dw_hi, g_dw_hi);
    cudaGetSymbolAddress((void**)&dw_lo, g_dw_lo);
    cudaGetSymbolAddress((void**)&wo_hi, g_wo_hi);
    cudaGetSymbolAddress((void**)&wo_lo, g_wo_lo);

    cudaFuncSetAttribute(gemm_f16x3<0,1>, cudaFuncAttributeMaxDynamicSharedMemorySize, G5_SMEM);
    cudaFuncSetAttribute(gemm_f16x3<0,XPROJ_SPLITK>, cudaFuncAttributeMaxDynamicSharedMemorySize, G5_SMEM);
    cudaFuncSetAttribute(gemm_f16x3<1,1>, cudaFuncAttributeMaxDynamicSharedMemorySize, G5_SMEM);
    cudaFuncSetAttribute(gemm_f16x3<2,1>, cudaFuncAttributeMaxDynamicSharedMemorySize, G5_SMEM);

    // 0. weight hi/lo splits
    split_kernel<<<(2*D_INNER*D_MODEL + 255)/256, 256>>>(W_in,  wi_hi, wi_lo, 2*D_INNER*D_MODEL);
    split_kernel<<<(XDBL_C*D_INNER   + 255)/256, 256>>>(x_proj, xp_hi, xp_lo, XDBL_C*D_INNER);
    split_kernel<<<(D_INNER*DT_RANK  + 255)/256, 256>>>(dt_w,   dw_hi, dw_lo, D_INNER*DT_RANK);
    split_kernel<<<(D_MODEL*D_INNER  + 255)/256, 256>>>(W_out,  wo_hi, wo_lo, D_MODEL*D_INNER);

    // 1. LayerNorm -> xn hi/lo
    ln_kernel<<<BL, 256>>>(x, ln_g, ln_b, xn_hi, xn_lo);

    // 2. xz = xn @ W_in^T   (4096 x 4096 x 1024)
    gemm_f16x3<0,1><<<dim3(2*D_INNER/128, BL/128), 256, G5_SMEM>>>(
        xn_hi, xn_lo, D_MODEL, wi_hi, wi_lo, D_MODEL,
        xz, 2*D_INNER, BL, 2*D_INNER, D_MODEL, nullptr, nullptr);

    // 3. causal depthwise conv + SiLU -> u (+ hi/lo)
    conv_silu_kernel<<<(BL*D_INNER + 255)/256, 256>>>(xz, conv_w, conv_b, u, u_hi, u_lo);

    // 4. x_dbl = u @ x_proj^T  (4096 x 96 x 2048), split-K=4
    gemm_f16x3<0,XPROJ_SPLITK><<<dim3(1, BL/128, XPROJ_SPLITK), 256, G5_SMEM>>>(
        u_hi, u_lo, D_INNER, xp_hi, xp_lo, D_INNER,
        part, XDBL_C, BL, XDBL_C, D_INNER, nullptr, nullptr);
    xproj_reduce<<<(BL*XDBL_C + 255)/256, 256>>>(part, xdbl, xd_hi, xd_lo);

    // 5. delta = softplus(dt_r @ dt_w^T + dt_b)  (4096 x 2048 x 64)
    gemm_f16x3<1,1><<<dim3(D_INNER/128, BL/128), 256, G5_SMEM>>>(
        xd_hi, xd_lo, XDBL_C, dw_hi, dw_lo, DT_RANK,
        dl, D_INNER, BL, D_INNER, DT_RANK, dt_b, nullptr);

    // 6. selective scan + fused gate -> y hi/lo
    scan_kernel<<<dim3(D_INNER/SC_DC, BSZ), SC_DC*D_STATE>>>(
        u, dl, xdbl, A_log, xz, D_prm, y_hi, y_lo);

    // 7. out = y @ W_out^T + x  (4096 x 1024 x 2048)
    gemm_f16x3<2,1><<<dim3(D_MODEL/128, BL/128), 256, G5_SMEM>>>(
        y_hi, y_lo, D_INNER, wo_hi, wo_lo, D_INNER,
        out, D_MODEL, BL, D_MODEL, D_INNER, nullptr, x);
}

// round 6
// speedup vs baseline: 2.6882x; 1.3112x over previous
#include <cuda_runtime.h>
#include <cuda_fp16.h>
#include <math.h>
#include <stdint.h>

#define D_MODEL 1024
#define D_INNER 2048
#define D_STATE 16
#define DT_RANK 64
#define CONV_K  4
#define BSZ     2
#define SEQ     2048
#define BL      (BSZ*SEQ)             // 4096
#define XDBL_C  (DT_RANK + 2*D_STATE) // 96
#define XPROJ_SPLITK 4

// ---------------- scratch (static device globals) ---------------------------
__device__ __align__(16) __half g_xn_hi[BL * D_MODEL];
__device__ __align__(16) __half g_xn_lo[BL * D_MODEL];
__device__ __align__(16) float  g_xz   [BL * 2 * D_INNER];
__device__ __align__(16) float  g_u    [BL * D_INNER];
__device__ __align__(16) __half g_u_hi [BL * D_INNER];
__device__ __align__(16) __half g_u_lo [BL * D_INNER];
__device__ __align__(16) float  g_xdbl [BL * XDBL_C];
__device__ __align__(16) __half g_xd_hi[BL * XDBL_C];
__device__ __align__(16) __half g_xd_lo[BL * XDBL_C];
__device__ __align__(16) float  g_part [XPROJ_SPLITK * BL * XDBL_C];
__device__ __align__(16) float  g_dl   [BL * D_INNER];
__device__ __align__(16) __half g_y_hi [BL * D_INNER];
__device__ __align__(16) __half g_y_lo [BL * D_INNER];
__device__ __align__(16) __half g_wi_hi[2 * D_INNER * D_MODEL];
__device__ __align__(16) __half g_wi_lo[2 * D_INNER * D_MODEL];
__device__ __align__(16) __half g_xp_hi[XDBL_C * D_INNER];
__device__ __align__(16) __half g_xp_lo[XDBL_C * D_INNER];
__device__ __align__(16) __half g_dw_hi[D_INNER * DT_RANK];
__device__ __align__(16) __half g_dw_lo[D_INNER * DT_RANK];
__device__ __align__(16) __half g_wo_hi[D_MODEL * D_INNER];
__device__ __align__(16) __half g_wo_lo[D_MODEL * D_INNER];

// ---------------- helpers ----------------------------------------------------
__device__ __forceinline__ void cp16(void* dst_smem, const void* src, int sz) {
    uint32_t d = (uint32_t)__cvta_generic_to_shared(dst_smem);
    asm volatile("cp.async.cg.shared.global [%0], [%1], 16, %2;\n"
                 :: "r"(d), "l"(src), "r"(sz));
}
__device__ __forceinline__ void cp_commit() {
    asm volatile("cp.async.commit_group;\n");
}
template<int N_> __device__ __forceinline__ void cp_wait() {
    asm volatile("cp.async.wait_group %0;\n" :: "n"(N_));
}
__device__ __forceinline__ void h_split(float x, __half& h, __half& l) {
    h = __float2half_rn(x);
    l = __float2half_rn(x - __half2float(h));
}
__device__ __forceinline__ void mma16(float* c, const uint32_t* a, const uint32_t* b) {
    asm volatile(
        "mma.sync.aligned.m16n8k16.row.col.f32.f16.f16.f32 "
        "{%0,%1,%2,%3}, {%4,%5,%6,%7}, {%8,%9}, {%0,%1,%2,%3};\n"
        : "+f"(c[0]), "+f"(c[1]), "+f"(c[2]), "+f"(c[3])
        : "r"(a[0]), "r"(a[1]), "r"(a[2]), "r"(a[3]), "r"(b[0]), "r"(b[1]));
}
#define LDSM_X4(r0, r1, r2, r3, addr)                                       \
    asm volatile("ldmatrix.sync.aligned.m8n8.x4.shared.b16 "                \
                 "{%0,%1,%2,%3}, [%4];"                                     \
                 : "=r"(r0), "=r"(r1), "=r"(r2), "=r"(r3) : "r"(addr))

// ---------------- FP16x3 tensor-core GEMM (m16n8k16 + ldmatrix) --------------
// C[M,N] = (Ahi+Alo)[M,K] @ ((Bhi+Blo)[N,K])^T  (3-term compensated)
// CTA 128x128, K chunk 32, 2-stage cp.async. 8 warps: warp tile 64x32
// (wm=(wid&1)*64, wn=(wid>>1)*32). smem rows padded to 40 halfs (conflict-free
// ldmatrix: banks {0,20,8,28,16,4,24,12} x4-word groups).
// EPI: 0 none, 1 softplus(acc+bias[n]), 2 acc+res[m*ldc+n]
#define RS_H    40
#define TILE_H  (128 * RS_H)      // 5120 halfs
#define STAGE_H (4 * TILE_H)      // 20480 halfs = 40KB
#define G6_SMEM (2 * STAGE_H * 2) // 81920 bytes

template<int EPI, int SPLITK>
__global__ __launch_bounds__(256, 2) void gemm_f16x3(
    const __half* __restrict__ Ahi, const __half* __restrict__ Alo, int lda,
    const __half* __restrict__ Bhi, const __half* __restrict__ Blo, int ldb,
    float* __restrict__ C, int ldc, int M, int N, int K,
    const float* __restrict__ bias, const float* __restrict__ res)
{
    extern __shared__ __half sm[];
    int tid = threadIdx.x;
    int m0 = blockIdx.y * 128;
    int n0 = blockIdx.x * 128;

    if (SPLITK > 1) {
        int z = blockIdx.z;
        int Ks = K / SPLITK;
        Ahi += (size_t)z * Ks; Alo += (size_t)z * Ks;
        Bhi += (size_t)z * Ks; Blo += (size_t)z * Ks;
        C += (size_t)z * M * ldc;
        K = Ks;
    }
    int KT = K / 32;

    int lane = tid & 31, wid = tid >> 5;
    int p = lane >> 2, q = lane & 3;
    int wm = (wid & 1) * 64;
    int wn = (wid >> 1) * 32;

    float acc[4][4][4];
    #pragma unroll
    for (int i = 0; i < 4; i++)
        #pragma unroll
        for (int j = 0; j < 4; j++)
            #pragma unroll
            for (int r = 0; r < 4; r++) acc[i][j][r] = 0.f;

    auto load_stage = [&](int kt, int slot) {
        __half* base = sm + slot * STAGE_H;
        int k0 = kt * 32;
        #pragma unroll
        for (int c = tid; c < 2048; c += 256) {
            int tile = c >> 9;            // 0:Ahi 1:Alo 2:Bhi 3:Blo
            int r = (c & 511) >> 2;
            int j = c & 3;
            __half* dst = base + tile * TILE_H + r * RS_H + j * 8;
            if (tile < 2) {
                const __half* src = (tile == 0 ? Ahi : Alo)
                                  + (size_t)(m0 + r) * lda + k0 + j * 8;
                cp16(dst, src, 16);
            } else {
                int n = n0 + r;
                int sz = (n < N) ? 16 : 0;
                int rr = sz ? n : 0;
                const __half* src = (tile == 2 ? Bhi : Blo)
                                  + (size_t)rr * ldb + k0 + j * 8;
                cp16(dst, src, sz);
            }
        }
    };

    load_stage(0, 0); cp_commit();
    if (KT > 1) load_stage(1, 1);
    cp_commit();

    // per-thread ldmatrix byte offsets (within tile)
    uint32_t smbase = (uint32_t)__cvta_generic_to_shared(sm);
    uint32_t a_off = ((wm + (lane & 15)) * RS_H + (lane >> 4) * 8) * 2;
    uint32_t b_off = ((wn + (lane >> 4) * 8 + (lane & 7)) * RS_H
                      + ((lane >> 3) & 1) * 8) * 2;

    for (int kt = 0; kt < KT; kt++) {
        int slot = kt & 1;
        cp_wait<1>();
        __syncthreads();

        uint32_t st = smbase + slot * STAGE_H * 2;
        uint32_t aHi = st + a_off;
        uint32_t aLo = aHi + TILE_H * 2;
        uint32_t bHi = st + 2 * TILE_H * 2 + b_off;
        uint32_t bLo = bHi + TILE_H * 2;

        #pragma unroll
        for (int s = 0; s < 2; s++) {
            uint32_t ko = s * 32;               // k16 step -> 32 bytes
            uint32_t bh[4][2], bl[4][2];
            LDSM_X4(bh[0][0], bh[0][1], bh[1][0], bh[1][1], bHi + ko);
            LDSM_X4(bh[2][0], bh[2][1], bh[3][0], bh[3][1], bHi + 16 * RS_H * 2 + ko);
            LDSM_X4(bl[0][0], bl[0][1], bl[1][0], bl[1][1], bLo + ko);
            LDSM_X4(bl[2][0], bl[2][1], bl[3][0], bl[3][1], bLo + 16 * RS_H * 2 + ko);
            #pragma unroll
            for (int mi = 0; mi < 4; mi++) {
                uint32_t ah[4], al[4];
                LDSM_X4(ah[0], ah[1], ah[2], ah[3], aHi + mi * 16 * RS_H * 2 + ko);
                LDSM_X4(al[0], al[1], al[2], al[3], aLo + mi * 16 * RS_H * 2 + ko);
                #pragma unroll
                for (int ni = 0; ni < 4; ni++) {
                    mma16(acc[mi][ni], ah, bh[ni]);
                    mma16(acc[mi][ni], al, bh[ni]);
                    mma16(acc[mi][ni], ah, bl[ni]);
                }
            }
        }
        __syncthreads();
        if (kt + 2 < KT) load_stage(kt + 2, slot);
        cp_commit();
    }

    // epilogue
    #pragma unroll
    for (int mi = 0; mi < 4; mi++) {
        int row = m0 + wm + mi * 16 + p;
        #pragma unroll
        for (int ni = 0; ni < 4; ni++) {
            int col = n0 + wn + ni * 8 + q * 2;
            if (col < N) {
                float v[4] = { acc[mi][ni][0], acc[mi][ni][1],
                               acc[mi][ni][2], acc[mi][ni][3] };
                if (EPI == 1) {
                    #pragma unroll
                    for (int r = 0; r < 4; r++) {
                        float t = v[r] + bias[col + (r & 1)];
                        float e = __expf(t);
                        v[r] = (t > 15.f) ? t : log1pf(e);
                    }
                } else if (EPI == 2) {
                    v[0] += res[(size_t)row * ldc + col];
                    v[1] += res[(size_t)row * ldc + col + 1];
                    v[2] += res[(size_t)(row + 8) * ldc + col];
                    v[3] += res[(size_t)(row + 8) * ldc + col + 1];
                }
                float* c0 = C + (size_t)row * ldc + col;
                float* c1 = C + (size_t)(row + 8) * ldc + col;
                c0[0] = v[0]; c0[1] = v[1];
                c1[0] = v[2]; c1[1] = v[3];
            }
        }
    }
}

// ---------------- weight hi/lo split -----------------------------------------
__global__ __launch_bounds__(256) void split_kernel(
    const float* __restrict__ src, __half* __restrict__ hi,
    __half* __restrict__ lo, int n)
{
    int i = blockIdx.x * 256 + threadIdx.x;
    if (i >= n) return;
    __half h, l;
    h_split(src[i], h, l);
    hi[i] = h; lo[i] = l;
}

// ---------------- LayerNorm (writes half hi/lo) ------------------------------
__global__ __launch_bounds__(256) void ln_kernel(
    const float* __restrict__ x, const float* __restrict__ g,
    const float* __restrict__ b, __half* __restrict__ ohi, __half* __restrict__ olo)
{
    int row = blockIdx.x;
    const float4* xr = (const float4*)(x + (size_t)row * D_MODEL);
    float4 v = xr[threadIdx.x];
    float s  = v.x + v.y + v.z + v.w;
    float ss = v.x*v.x + v.y*v.y + v.z*v.z + v.w*v.w;
    #pragma unroll
    for (int o = 16; o; o >>= 1) {
        s  += __shfl_xor_sync(0xffffffffu, s, o);
        ss += __shfl_xor_sync(0xffffffffu, ss, o);
    }
    __shared__ float red[16];
    __shared__ float mu_s, rstd_s;
    int w = threadIdx.x >> 5, lane = threadIdx.x & 31;
    if (lane == 0) { red[w] = s; red[8 + w] = ss; }
    __syncthreads();
    if (threadIdx.x == 0) {
        float S = 0.f, SS = 0.f;
        #pragma unroll
        for (int i = 0; i < 8; i++) { S += red[i]; SS += red[8 + i]; }
        float mu = S * (1.f / D_MODEL);
        float var = SS * (1.f / D_MODEL) - mu * mu;
        mu_s = mu; rstd_s = rsqrtf(var + 1e-5f);
    }
    __syncthreads();
    float mu = mu_s, r = rstd_s;
    float4 gv = ((const float4*)g)[threadIdx.x];
    float4 bv = ((const float4*)b)[threadIdx.x];
    float o0 = (v.x - mu) * r * gv.x + bv.x;
    float o1 = (v.y - mu) * r * gv.y + bv.y;
    float o2 = (v.z - mu) * r * gv.z + bv.z;
    float o3 = (v.w - mu) * r * gv.w + bv.w;
    __half h0, l0, h1, l1, h2, l2, h3, l3;
    h_split(o0, h0, l0); h_split(o1, h1, l1);
    h_split(o2, h2, l2); h_split(o3, h3, l3);
    __half2* ph = (__half2*)(ohi + (size_t)row * D_MODEL);
    __half2* pl = (__half2*)(olo + (size_t)row * D_MODEL);
    ph[2*threadIdx.x]   = __halves2half2(h0, h1);
    ph[2*threadIdx.x+1] = __halves2half2(h2, h3);
    pl[2*threadIdx.x]   = __halves2half2(l0, l1);
    pl[2*threadIdx.x+1] = __halves2half2(l2, l3);
}

// ---------------- split-K reduce for x_proj -----------------------------------
__global__ __launch_bounds__(256) void xproj_reduce(
    const float* __restrict__ part, float* __restrict__ out,
    __half* __restrict__ ohi, __half* __restrict__ olo)
{
    int i = blockIdx.x * 256 + threadIdx.x;
    if (i >= BL * XDBL_C) return;
    const int stride = BL * XDBL_C;
    float s = part[i];
    #pragma unroll
    for (int z = 1; z < XPROJ_SPLITK; z++) s += part[i + z * stride];
    out[i] = s;
    __half h, l;
    h_split(s, h, l);
    ohi[i] = h; olo[i] = l;
}

// ---------------- causal depthwise conv (K=4) + SiLU --------------------------
__global__ __launch_bounds__(256) void conv_silu_kernel(
    const float* __restrict__ xz, const float* __restrict__ w,
    const float* __restrict__ bias, float* __restrict__ u,
    __half* __restrict__ uhi, __half* __restrict__ ulo)
{
    int idx = blockIdx.x * 256 + threadIdx.x;
    if (idx >= BL * D_INNER) return;
    int d = idx % D_INNER;
    int t = (idx / D_INNER) % SEQ;
    int b = idx / (D_INNER * SEQ);
    float acc = bias[d];
    const float* wr = w + d * CONV_K;
    #pragma unroll
    for (int k = 0; k < CONV_K; k++) {
        int ts = t - (CONV_K - 1) + k;
        if (ts >= 0)
            acc += wr[k] * xz[(size_t)(b * SEQ + ts) * (2 * D_INNER) + d];
    }
    float sg = 1.f / (1.f + __expf(-acc));
    float val = acc * sg;
    u[idx] = val;
    __half h, l;
    h_split(val, h, l);
    uhi[idx] = h; ulo[idx] = l;
}

// ---------------- selective scan (gate fused; writes half hi/lo) --------------
#define SC_DC 32
#define SC_TC 64
__global__ __launch_bounds__(SC_DC * D_STATE) void scan_kernel(
    const float* __restrict__ u, const float* __restrict__ dl,
    const float* __restrict__ xdbl, const float* __restrict__ A_log,
    const float* __restrict__ xz, const float* __restrict__ Dp,
    __half* __restrict__ yhi, __half* __restrict__ ylo)
{
    __shared__ float u_s [SC_TC][SC_DC];
    __shared__ float dl_s[SC_TC][SC_DC];
    __shared__ float B_s [SC_TC][D_STATE];
    __shared__ float C_s [SC_TC][D_STATE];
    __shared__ float y_s [SC_TC][SC_DC];

    int b  = blockIdx.y;
    int d0 = blockIdx.x * SC_DC;
    int tid = threadIdx.x;
    int g = tid >> 4;
    int n = tid & 15;
    int d = d0 + g;

    float a = -expf(A_log[d * D_STATE + n]);
    float s = 0.f;

    for (int t0 = 0; t0 < SEQ; t0 += SC_TC) {
        for (int i = tid; i < SC_TC * SC_DC; i += SC_DC * D_STATE) {
            int tt = i / SC_DC, gg = i % SC_DC;
            int gi = (b * SEQ + t0 + tt) * D_INNER + d0 + gg;
            u_s [tt][gg] = u [gi];
            dl_s[tt][gg] = dl[gi];
        }
        for (int i = tid; i < SC_TC * D_STATE; i += SC_DC * D_STATE) {
            int tt = i / D_STATE, nn = i % D_STATE;
            const float* r = xdbl + (size_t)(b * SEQ + t0 + tt) * XDBL_C + DT_RANK;
            B_s[tt][nn] = r[nn];
            C_s[tt][nn] = r[D_STATE + nn];
        }
        __syncthreads();
        #pragma unroll 4
        for (int t = 0; t < SC_TC; t++) {
            float dlt = dl_s[t][g];
            float dA  = __expf(dlt * a);
            float dbu = dlt * B_s[t][n] * u_s[t][g];
            s = fmaf(dA, s, dbu);
            float part = s * C_s[t][n];
            part += __shfl_xor_sync(0xffffffffu, part, 8);
            part += __shfl_xor_sync(0xffffffffu, part, 4);
            part += __shfl_xor_sync(0xffffffffu, part, 2);
            part += __shfl_xor_sync(0xffffffffu, part, 1);
            if (n == 0) y_s[t][g] = part;
        }
        __syncthreads();
        for (int i = tid; i < SC_TC * SC_DC; i += SC_DC * D_STATE) {
            int tt = i / SC_DC, gg = i % SC_DC;
            int rowg = b * SEQ + t0 + tt;
            float z = xz[(size_t)rowg * (2 * D_INNER) + D_INNER + d0 + gg];
            float sz = z / (1.f + __expf(-z));
            float val = (y_s[tt][gg] + u_s[tt][gg] * Dp[d0 + gg]) * sz;
            __half h, l;
            h_split(val, h, l);
            size_t oi = (size_t)rowg * D_INNER + d0 + gg;
            yhi[oi] = h; ylo[oi] = l;
        }
        __syncthreads();
    }
}

// ---------------- launch ------------------------------------------------------
extern "C" void kernel_launch(void* const* d_in, const int* in_sizes, int n_in,
                              void* d_out, int out_size)
{
    const float* x      = (const float*)d_in[0];
    const float* ln_g   = (const float*)d_in[1];
    const float* ln_b   = (const float*)d_in[2];
    const float* W_in   = (const float*)d_in[3];
    const float* conv_w = (const float*)d_in[4];
    const float* conv_b = (const float*)d_in[5];
    const float* A_log  = (const float*)d_in[6];
    const float* D_prm  = (const float*)d_in[7];
    const float* x_proj = (const float*)d_in[8];
    const float* dt_w   = (const float*)d_in[9];
    const float* dt_b   = (const float*)d_in[10];
    const float* W_out  = (const float*)d_in[11];
    float* out = (float*)d_out;

    __half *xn_hi, *xn_lo, *u_hi, *u_lo, *xd_hi, *xd_lo, *y_hi, *y_lo;
    __half *wi_hi, *wi_lo, *xp_hi, *xp_lo, *dw_hi, *dw_lo, *wo_hi, *wo_lo;
    float *xz, *u, *xdbl, *part, *dl;
    cudaGetSymbolAddress((void**)&xn_hi, g_xn_hi);
    cudaGetSymbolAddress((void**)&xn_lo, g_xn_lo);
    cudaGetSymbolAddress((void**)&xz,    g_xz);
    cudaGetSymbolAddress((void**)&u,     g_u);
    cudaGetSymbolAddress((void**)&u_hi,  g_u_hi);
    cudaGetSymbolAddress((void**)&u_lo,  g_u_lo);
    cudaGetSymbolAddress((void**)&xdbl,  g_xdbl);
    cudaGetSymbolAddress((void**)&xd_hi, g_xd_hi);
    cudaGetSymbolAddress((void**)&xd_lo, g_xd_lo);
    cudaGetSymbolAddress((void**)&part,  g_part);
    cudaGetSymbolAddress((void**)&dl,    g_dl);
    cudaGetSymbolAddress((void**)&y_hi,  g_y_hi);
    cudaGetSymbolAddress((void**)&y_lo,  g_y_lo);
    cudaGetSymbolAddress((void**)&wi_hi, g_wi_hi);
    cudaGetSymbolAddress((void**)&wi_lo, g_wi_lo);
    cudaGetSymbolAddress((void**)&xp_hi, g_xp_hi);
    cudaGetSymbolAddress((void**)&xp_lo, g_xp_lo);
    cudaGetSymbolAddress((void**)&dw_hi, g_dw_hi);
    cudaGetSymbolAddress((void**)&dw_lo, g_dw_lo);
    cudaGetSymbolAddress((void**)&wo_hi, g_wo_hi);
    cudaGetSymbolAddress((void**)&wo_lo, g_wo_lo);

    cudaFuncSetAttribute(gemm_f16x3<0,1>, cudaFuncAttributeMaxDynamicSharedMemorySize, G6_SMEM);
    cudaFuncSetAttribute(gemm_f16x3<0,XPROJ_SPLITK>, cudaFuncAttributeMaxDynamicSharedMemorySize, G6_SMEM);
    cudaFuncSetAttribute(gemm_f16x3<1,1>, cudaFuncAttributeMaxDynamicSharedMemorySize, G6_SMEM);
    cudaFuncSetAttribute(gemm_f16x3<2,1>, cudaFuncAttributeMaxDynamicSharedMemorySize, G6_SMEM);

    // 0. weight hi/lo splits
    split_kernel<<<(2*D_INNER*D_MODEL + 255)/256, 256>>>(W_in,  wi_hi, wi_lo, 2*D_INNER*D_MODEL);
    split_kernel<<<(XDBL_C*D_INNER   + 255)/256, 256>>>(x_proj, xp_hi, xp_lo, XDBL_C*D_INNER);
    split_kernel<<<(D_INNER*DT_RANK  + 255)/256, 256>>>(dt_w,   dw_hi, dw_lo, D_INNER*DT_RANK);
    split_kernel<<<(D_MODEL*D_INNER  + 255)/256, 256>>>(W_out,  wo_hi, wo_lo, D_MODEL*D_INNER);

    // 1. LayerNorm -> xn hi/lo
    ln_kernel<<<BL, 256>>>(x, ln_g, ln_b, xn_hi, xn_lo);

    // 2. xz = xn @ W_in^T   (4096 x 4096 x 1024)
    gemm_f16x3<0,1><<<dim3(2*D_INNER/128, BL/128), 256, G6_SMEM>>>(
        xn_hi, xn_lo, D_MODEL, wi_hi, wi_lo, D_MODEL,
        xz, 2*D_INNER, BL, 2*D_INNER, D_MODEL, nullptr, nullptr);

    // 3. causal depthwise conv + SiLU -> u (+ hi/lo)
    conv_silu_kernel<<<(BL*D_INNER + 255)/256, 256>>>(xz, conv_w, conv_b, u, u_hi, u_lo);

    // 4. x_dbl = u @ x_proj^T  (4096 x 96 x 2048), split-K=4
    gemm_f16x3<0,XPROJ_SPLITK><<<dim3(1, BL/128, XPROJ_SPLITK), 256, G6_SMEM>>>(
        u_hi, u_lo, D_INNER, xp_hi, xp_lo, D_INNER,
        part, XDBL_C, BL, XDBL_C, D_INNER, nullptr, nullptr);
    xproj_reduce<<<(BL*XDBL_C + 255)/256, 256>>>(part, xdbl, xd_hi, xd_lo);

    // 5. delta = softplus(dt_r @ dt_w^T + dt_b)  (4096 x 2048 x 64)
    gemm_f16x3<1,1><<<dim3(D_INNER/128, BL/128), 256, G6_SMEM>>>(
        xd_hi, xd_lo, XDBL_C, dw_hi, dw_lo, DT_RANK,
        dl, D_INNER, BL, D_INNER, DT_RANK, dt_b, nullptr);

    // 6. selective scan + fused gate -> y hi/lo
    scan_kernel<<<dim3(D_INNER/SC_DC, BSZ), SC_DC*D_STATE>>>(
        u, dl, xdbl, A_log, xz, D_prm, y_hi, y_lo);

    // 7. out = y @ W_out^T + x  (4096 x 1024 x 2048)
    gemm_f16x3<2,1><<<dim3(D_MODEL/128, BL/128), 256, G6_SMEM>>>(
        y_hi, y_lo, D_INNER, wo_hi, wo_lo, D_INNER,
        out, D_MODEL, BL, D_MODEL, D_INNER, nullptr, x);
}

// round 7
// speedup vs baseline: 3.0464x; 1.1333x over previous
#include <cuda_runtime.h>
#include <cuda_fp16.h>
#include <math.h>
#include <stdint.h>

#define D_MODEL 1024
#define D_INNER 2048
#define D_STATE 16
#define DT_RANK 64
#define CONV_K  4
#define BSZ     2
#define SEQ     2048
#define BL      (BSZ*SEQ)             // 4096
#define XDBL_C  (DT_RANK + 2*D_STATE) // 96
#define XPROJ_SPLITK 4

// ---------------- scratch (static device globals) ---------------------------
__device__ __align__(16) __half g_xn_hi[BL * D_MODEL];
__device__ __align__(16) __half g_xn_lo[BL * D_MODEL];
__device__ __align__(16) float  g_xz   [BL * 2 * D_INNER];
__device__ __align__(16) float  g_u    [BL * D_INNER];
__device__ __align__(16) __half g_u_hi [BL * D_INNER];
__device__ __align__(16) __half g_u_lo [BL * D_INNER];
__device__ __align__(16) float  g_xdbl [BL * XDBL_C];
__device__ __align__(16) __half g_xd_hi[BL * XDBL_C];
__device__ __align__(16) __half g_xd_lo[BL * XDBL_C];
__device__ __align__(16) float  g_part [XPROJ_SPLITK * BL * XDBL_C];
__device__ __align__(16) float  g_dl   [BL * D_INNER];
__device__ __align__(16) __half g_y_hi [BL * D_INNER];
__device__ __align__(16) __half g_y_lo [BL * D_INNER];
__device__ __align__(16) __half g_wi_hi[2 * D_INNER * D_MODEL];
__device__ __align__(16) __half g_wi_lo[2 * D_INNER * D_MODEL];
__device__ __align__(16) __half g_xp_hi[XDBL_C * D_INNER];
__device__ __align__(16) __half g_xp_lo[XDBL_C * D_INNER];
__device__ __align__(16) __half g_dw_hi[D_INNER * DT_RANK];
__device__ __align__(16) __half g_dw_lo[D_INNER * DT_RANK];
__device__ __align__(16) __half g_wo_hi[D_MODEL * D_INNER];
__device__ __align__(16) __half g_wo_lo[D_MODEL * D_INNER];

// ---------------- helpers ----------------------------------------------------
__device__ __forceinline__ void cp16(void* dst_smem, const void* src, int sz) {
    uint32_t d = (uint32_t)__cvta_generic_to_shared(dst_smem);
    asm volatile("cp.async.cg.shared.global [%0], [%1], 16, %2;\n"
                 :: "r"(d), "l"(src), "r"(sz));
}
__device__ __forceinline__ void cp_commit() {
    asm volatile("cp.async.commit_group;\n");
}
template<int N_> __device__ __forceinline__ void cp_wait() {
    asm volatile("cp.async.wait_group %0;\n" :: "n"(N_));
}
__device__ __forceinline__ void h_split(float x, __half& h, __half& l) {
    h = __float2half_rn(x);
    l = __float2half_rn(x - __half2float(h));
}
// split float4 -> packed 4-half hi (uint2) and lo (uint2)
__device__ __forceinline__ void h_split4(float4 v, uint2& hi, uint2& lo) {
    __half h0,l0,h1,l1,h2,l2,h3,l3;
    h_split(v.x,h0,l0); h_split(v.y,h1,l1);
    h_split(v.z,h2,l2); h_split(v.w,h3,l3);
    __half2 ha = __halves2half2(h0,h1), hb = __halves2half2(h2,h3);
    __half2 la = __halves2half2(l0,l1), lb = __halves2half2(l2,l3);
    hi.x = *(uint32_t*)&ha; hi.y = *(uint32_t*)&hb;
    lo.x = *(uint32_t*)&la; lo.y = *(uint32_t*)&lb;
}
__device__ __forceinline__ void mma16(float* c, const uint32_t* a, const uint32_t* b) {
    asm volatile(
        "mma.sync.aligned.m16n8k16.row.col.f32.f16.f16.f32 "
        "{%0,%1,%2,%3}, {%4,%5,%6,%7}, {%8,%9}, {%0,%1,%2,%3};\n"
        : "+f"(c[0]), "+f"(c[1]), "+f"(c[2]), "+f"(c[3])
        : "r"(a[0]), "r"(a[1]), "r"(a[2]), "r"(a[3]), "r"(b[0]), "r"(b[1]));
}
#define LDSM_X4(r0, r1, r2, r3, addr)                                       \
    asm volatile("ldmatrix.sync.aligned.m8n8.x4.shared.b16 "                \
                 "{%0,%1,%2,%3}, [%4];"                                     \
                 : "=r"(r0), "=r"(r1), "=r"(r2), "=r"(r3) : "r"(addr))

// ---------------- FP16x3 tensor-core GEMM (m16n8k16 + ldmatrix) --------------
#define RS_H    40
#define TILE_H  (128 * RS_H)
#define STAGE_H (4 * TILE_H)
#define G6_SMEM (2 * STAGE_H * 2)

template<int EPI, int SPLITK>
__global__ __launch_bounds__(256, 2) void gemm_f16x3(
    const __half* __restrict__ Ahi, const __half* __restrict__ Alo, int lda,
    const __half* __restrict__ Bhi, const __half* __restrict__ Blo, int ldb,
    float* __restrict__ C, int ldc, int M, int N, int K,
    const float* __restrict__ bias, const float* __restrict__ res)
{
    extern __shared__ __half sm[];
    int tid = threadIdx.x;
    int m0 = blockIdx.y * 128;
    int n0 = blockIdx.x * 128;

    if (SPLITK > 1) {
        int z = blockIdx.z;
        int Ks = K / SPLITK;
        Ahi += (size_t)z * Ks; Alo += (size_t)z * Ks;
        Bhi += (size_t)z * Ks; Blo += (size_t)z * Ks;
        C += (size_t)z * M * ldc;
        K = Ks;
    }
    int KT = K / 32;

    int lane = tid & 31, wid = tid >> 5;
    int p = lane >> 2, q = lane & 3;
    int wm = (wid & 1) * 64;
    int wn = (wid >> 1) * 32;

    float acc[4][4][4];
    #pragma unroll
    for (int i = 0; i < 4; i++)
        #pragma unroll
        for (int j = 0; j < 4; j++)
            #pragma unroll
            for (int r = 0; r < 4; r++) acc[i][j][r] = 0.f;

    auto load_stage = [&](int kt, int slot) {
        __half* base = sm + slot * STAGE_H;
        int k0 = kt * 32;
        #pragma unroll
        for (int c = tid; c < 2048; c += 256) {
            int tile = c >> 9;
            int r = (c & 511) >> 2;
            int j = c & 3;
            __half* dst = base + tile * TILE_H + r * RS_H + j * 8;
            if (tile < 2) {
                const __half* src = (tile == 0 ? Ahi : Alo)
                                  + (size_t)(m0 + r) * lda + k0 + j * 8;
                cp16(dst, src, 16);
            } else {
                int n = n0 + r;
                int sz = (n < N) ? 16 : 0;
                int rr = sz ? n : 0;
                const __half* src = (tile == 2 ? Bhi : Blo)
                                  + (size_t)rr * ldb + k0 + j * 8;
                cp16(dst, src, sz);
            }
        }
    };

    load_stage(0, 0); cp_commit();
    if (KT > 1) load_stage(1, 1);
    cp_commit();

    uint32_t smbase = (uint32_t)__cvta_generic_to_shared(sm);
    uint32_t a_off = ((wm + (lane & 15)) * RS_H + (lane >> 4) * 8) * 2;
    uint32_t b_off = ((wn + (lane >> 4) * 8 + (lane & 7)) * RS_H
                      + ((lane >> 3) & 1) * 8) * 2;

    for (int kt = 0; kt < KT; kt++) {
        int slot = kt & 1;
        cp_wait<1>();
        __syncthreads();

        uint32_t st = smbase + slot * STAGE_H * 2;
        uint32_t aHi = st + a_off;
        uint32_t aLo = aHi + TILE_H * 2;
        uint32_t bHi = st + 2 * TILE_H * 2 + b_off;
        uint32_t bLo = bHi + TILE_H * 2;

        #pragma unroll
        for (int s = 0; s < 2; s++) {
            uint32_t ko = s * 32;
            uint32_t bh[4][2], bl[4][2];
            LDSM_X4(bh[0][0], bh[0][1], bh[1][0], bh[1][1], bHi + ko);
            LDSM_X4(bh[2][0], bh[2][1], bh[3][0], bh[3][1], bHi + 16 * RS_H * 2 + ko);
            LDSM_X4(bl[0][0], bl[0][1], bl[1][0], bl[1][1], bLo + ko);
            LDSM_X4(bl[2][0], bl[2][1], bl[3][0], bl[3][1], bLo + 16 * RS_H * 2 + ko);
            #pragma unroll
            for (int mi = 0; mi < 4; mi++) {
                uint32_t ah[4], al[4];
                LDSM_X4(ah[0], ah[1], ah[2], ah[3], aHi + mi * 16 * RS_H * 2 + ko);
                LDSM_X4(al[0], al[1], al[2], al[3], aLo + mi * 16 * RS_H * 2 + ko);
                #pragma unroll
                for (int ni = 0; ni < 4; ni++) {
                    mma16(acc[mi][ni], ah, bh[ni]);
                    mma16(acc[mi][ni], al, bh[ni]);
                    mma16(acc[mi][ni], ah, bl[ni]);
                }
            }
        }
        __syncthreads();
        if (kt + 2 < KT) load_stage(kt + 2, slot);
        cp_commit();
    }

    #pragma unroll
    for (int mi = 0; mi < 4; mi++) {
        int row = m0 + wm + mi * 16 + p;
        #pragma unroll
        for (int ni = 0; ni < 4; ni++) {
            int col = n0 + wn + ni * 8 + q * 2;
            if (col < N) {
                float v[4] = { acc[mi][ni][0], acc[mi][ni][1],
                               acc[mi][ni][2], acc[mi][ni][3] };
                if (EPI == 1) {
                    #pragma unroll
                    for (int r = 0; r < 4; r++) {
                        float t = v[r] + bias[col + (r & 1)];
                        float e = __expf(t);
                        v[r] = (t > 15.f) ? t : log1pf(e);
                    }
                } else if (EPI == 2) {
                    v[0] += res[(size_t)row * ldc + col];
                    v[1] += res[(size_t)row * ldc + col + 1];
                    v[2] += res[(size_t)(row + 8) * ldc + col];
                    v[3] += res[(size_t)(row + 8) * ldc + col + 1];
                }
                float* c0 = C + (size_t)row * ldc + col;
                float* c1 = C + (size_t)(row + 8) * ldc + col;
                c0[0] = v[0]; c0[1] = v[1];
                c1[0] = v[2]; c1[1] = v[3];
            }
        }
    }
}

// ---------------- weight hi/lo split (8 elems/thread, 16B stores) ------------
__global__ __launch_bounds__(256) void split_kernel(
    const float* __restrict__ src, __half* __restrict__ hi,
    __half* __restrict__ lo, int n)   // n divisible by 8
{
    int i = (blockIdx.x * 256 + threadIdx.x) * 8;
    if (i >= n) return;
    float4 a = *(const float4*)(src + i);
    float4 b = *(const float4*)(src + i + 4);
    uint2 h0, l0, h1, l1;
    h_split4(a, h0, l0);
    h_split4(b, h1, l1);
    *(uint4*)(hi + i) = make_uint4(h0.x, h0.y, h1.x, h1.y);
    *(uint4*)(lo + i) = make_uint4(l0.x, l0.y, l1.x, l1.y);
}

// ---------------- LayerNorm (8B packed half stores) --------------------------
__global__ __launch_bounds__(256) void ln_kernel(
    const float* __restrict__ x, const float* __restrict__ g,
    const float* __restrict__ b, __half* __restrict__ ohi, __half* __restrict__ olo)
{
    int row = blockIdx.x;
    const float4* xr = (const float4*)(x + (size_t)row * D_MODEL);
    float4 v = xr[threadIdx.x];
    float s  = v.x + v.y + v.z + v.w;
    float ss = v.x*v.x + v.y*v.y + v.z*v.z + v.w*v.w;
    #pragma unroll
    for (int o = 16; o; o >>= 1) {
        s  += __shfl_xor_sync(0xffffffffu, s, o);
        ss += __shfl_xor_sync(0xffffffffu, ss, o);
    }
    __shared__ float red[16];
    __shared__ float mu_s, rstd_s;
    int w = threadIdx.x >> 5, lane = threadIdx.x & 31;
    if (lane == 0) { red[w] = s; red[8 + w] = ss; }
    __syncthreads();
    if (threadIdx.x == 0) {
        float S = 0.f, SS = 0.f;
        #pragma unroll
        for (int i = 0; i < 8; i++) { S += red[i]; SS += red[8 + i]; }
        float mu = S * (1.f / D_MODEL);
        float var = SS * (1.f / D_MODEL) - mu * mu;
        mu_s = mu; rstd_s = rsqrtf(var + 1e-5f);
    }
    __syncthreads();
    float mu = mu_s, r = rstd_s;
    float4 gv = ((const float4*)g)[threadIdx.x];
    float4 bv = ((const float4*)b)[threadIdx.x];
    float4 o;
    o.x = (v.x - mu) * r * gv.x + bv.x;
    o.y = (v.y - mu) * r * gv.y + bv.y;
    o.z = (v.z - mu) * r * gv.z + bv.z;
    o.w = (v.w - mu) * r * gv.w + bv.w;
    uint2 h, l;
    h_split4(o, h, l);
    ((uint2*)(ohi + (size_t)row * D_MODEL))[threadIdx.x] = h;
    ((uint2*)(olo + (size_t)row * D_MODEL))[threadIdx.x] = l;
}

// ---------------- split-K reduce for x_proj (float4) --------------------------
__global__ __launch_bounds__(256) void xproj_reduce(
    const float* __restrict__ part, float* __restrict__ out,
    __half* __restrict__ ohi, __half* __restrict__ olo)
{
    int i = (blockIdx.x * 256 + threadIdx.x) * 4;
    if (i >= BL * XDBL_C) return;
    const int stride = BL * XDBL_C;
    float4 s = *(const float4*)(part + i);
    #pragma unroll
    for (int z = 1; z < XPROJ_SPLITK; z++) {
        float4 p = *(const float4*)(part + z * stride + i);
        s.x += p.x; s.y += p.y; s.z += p.z; s.w += p.w;
    }
    *(float4*)(out + i) = s;
    uint2 h, l;
    h_split4(s, h, l);
    *(uint2*)(ohi + i) = h;
    *(uint2*)(olo + i) = l;
}

// ---------------- causal depthwise conv (K=4) + SiLU, 4 ch/thread ------------
__global__ __launch_bounds__(256) void conv_silu_kernel(
    const float* __restrict__ xz, const float* __restrict__ w,
    const float* __restrict__ bias, float* __restrict__ u,
    __half* __restrict__ uhi, __half* __restrict__ ulo)
{
    int idx = blockIdx.x * 256 + threadIdx.x;       // over BL*D_INNER/4
    if (idx >= BL * D_INNER / 4) return;
    int d4 = (idx * 4) % D_INNER;
    int t  = (idx * 4 / D_INNER) % SEQ;
    int b  = idx * 4 / (D_INNER * SEQ);

    float4 acc = *(const float4*)(bias + d4);
    float4 wr[4];
    #pragma unroll
    for (int c = 0; c < 4; c++) wr[c] = *(const float4*)(w + (d4 + c) * CONV_K);

    #pragma unroll
    for (int k = 0; k < CONV_K; k++) {
        int ts = t - (CONV_K - 1) + k;
        if (ts >= 0) {
            float4 xv = *(const float4*)(xz + (size_t)(b * SEQ + ts) * (2 * D_INNER) + d4);
            acc.x += ((const float*)&wr[0])[k] * xv.x;
            acc.y += ((const float*)&wr[1])[k] * xv.y;
            acc.z += ((const float*)&wr[2])[k] * xv.z;
            acc.w += ((const float*)&wr[3])[k] * xv.w;
        }
    }
    float4 val;
    val.x = acc.x / (1.f + __expf(-acc.x));
    val.y = acc.y / (1.f + __expf(-acc.y));
    val.z = acc.z / (1.f + __expf(-acc.z));
    val.w = acc.w / (1.f + __expf(-acc.w));
    size_t oi = (size_t)(b * SEQ + t) * D_INNER + d4;
    *(float4*)(u + oi) = val;
    uint2 h, l;
    h_split4(val, h, l);
    *(uint2*)(uhi + oi) = h;
    *(uint2*)(ulo + oi) = l;
}

// ---------------- selective scan (gate fused; vectorized I/O) -----------------
#define SC_DC 32
#define SC_TC 64
__global__ __launch_bounds__(SC_DC * D_STATE) void scan_kernel(
    const float* __restrict__ u, const float* __restrict__ dl,
    const float* __restrict__ xdbl, const float* __restrict__ A_log,
    const float* __restrict__ xz, const float* __restrict__ Dp,
    __half* __restrict__ yhi, __half* __restrict__ ylo)
{
    __shared__ float u_s [SC_TC][SC_DC];
    __shared__ float dl_s[SC_TC][SC_DC];
    __shared__ float B_s [SC_TC][D_STATE];
    __shared__ float C_s [SC_TC][D_STATE];
    __shared__ float y_s [SC_TC][SC_DC];

    int b  = blockIdx.y;
    int d0 = blockIdx.x * SC_DC;
    int tid = threadIdx.x;
    int g = tid >> 4;
    int n = tid & 15;
    int d = d0 + g;

    float a = -expf(A_log[d * D_STATE + n]);
    float s = 0.f;
    float Dpr = Dp[d0 + (tid & 31)];   // for gate stage: thread covers gg = tid&31? no — gate uses vec4 below

    for (int t0 = 0; t0 < SEQ; t0 += SC_TC) {
        // stage u, dl: 64x32 floats = 2048 = 512 thr * float4
        {
            int i = tid * 4;
            int tt = i >> 5, gg = i & 31;
            size_t gi = (size_t)(b * SEQ + t0 + tt) * D_INNER + d0 + gg;
            *(float4*)&u_s [tt][gg] = *(const float4*)(u  + gi);
            *(float4*)&dl_s[tt][gg] = *(const float4*)(dl + gi);
        }
        // stage B,C: 64 rows x 32 floats (B 16 | C 16) = 2048 = 512 thr * float4
        {
            int i = tid * 4;
            int tt = i >> 5, pos = i & 31;
            const float* r = xdbl + (size_t)(b * SEQ + t0 + tt) * XDBL_C + DT_RANK;
            float4 v = *(const float4*)(r + pos);
            if (pos < 16) *(float4*)&B_s[tt][pos] = v;
            else          *(float4*)&C_s[tt][pos - 16] = v;
        }
        __syncthreads();
        #pragma unroll 4
        for (int t = 0; t < SC_TC; t++) {
            float dlt = dl_s[t][g];
            float dA  = __expf(dlt * a);
            float dbu = dlt * B_s[t][n] * u_s[t][g];
            s = fmaf(dA, s, dbu);
            float part = s * C_s[t][n];
            part += __shfl_xor_sync(0xffffffffu, part, 8);
            part += __shfl_xor_sync(0xffffffffu, part, 4);
            part += __shfl_xor_sync(0xffffffffu, part, 2);
            part += __shfl_xor_sync(0xffffffffu, part, 1);
            if (n == 0) y_s[t][g] = part;
        }
        __syncthreads();
        // fused gate, vectorized: thread handles 4 consecutive gg
        {
            int i = tid * 4;
            int tt = i >> 5, gg = i & 31;
            int rowg = b * SEQ + t0 + tt;
            float4 z = *(const float4*)(xz + (size_t)rowg * (2 * D_INNER) + D_INNER + d0 + gg);
            float4 uu = *(const float4*)&u_s[tt][gg];
            float4 yy = *(const float4*)&y_s[tt][gg];
            float4 dp = *(const float4*)(Dp + d0 + gg);
            float4 val;
            val.x = (yy.x + uu.x * dp.x) * (z.x / (1.f + __expf(-z.x)));
            val.y = (yy.y + uu.y * dp.y) * (z.y / (1.f + __expf(-z.y)));
            val.z = (yy.z + uu.z * dp.z) * (z.z / (1.f + __expf(-z.z)));
            val.w = (yy.w + uu.w * dp.w) * (z.w / (1.f + __expf(-z.w)));
            uint2 h, l;
            h_split4(val, h, l);
            size_t oi = (size_t)rowg * D_INNER + d0 + gg;
            *(uint2*)(yhi + oi) = h;
            *(uint2*)(ylo + oi) = l;
        }
        __syncthreads();
    }
    (void)Dpr;
}

// ---------------- launch ------------------------------------------------------
extern "C" void kernel_launch(void* const* d_in, const int* in_sizes, int n_in,
                              void* d_out, int out_size)
{
    const float* x      = (const float*)d_in[0];
    const float* ln_g   = (const float*)d_in[1];
    const float* ln_b   = (const float*)d_in[2];
    const float* W_in   = (const float*)d_in[3];
    const float* conv_w = (const float*)d_in[4];
    const float* conv_b = (const float*)d_in[5];
    const float* A_log  = (const float*)d_in[6];
    const float* D_prm  = (const float*)d_in[7];
    const float* x_proj = (const float*)d_in[8];
    const float* dt_w   = (const float*)d_in[9];
    const float* dt_b   = (const float*)d_in[10];
    const float* W_out  = (const float*)d_in[11];
    float* out = (float*)d_out;

    __half *xn_hi, *xn_lo, *u_hi, *u_lo, *xd_hi, *xd_lo, *y_hi, *y_lo;
    __half *wi_hi, *wi_lo, *xp_hi, *xp_lo, *dw_hi, *dw_lo, *wo_hi, *wo_lo;
    float *xz, *u, *xdbl, *part, *dl;
    cudaGetSymbolAddress((void**)&xn_hi, g_xn_hi);
    cudaGetSymbolAddress((void**)&xn_lo, g_xn_lo);
    cudaGetSymbolAddress((void**)&xz,    g_xz);
    cudaGetSymbolAddress((void**)&u,     g_u);
    cudaGetSymbolAddress((void**)&u_hi,  g_u_hi);
    cudaGetSymbolAddress((void**)&u_lo,  g_u_lo);
    cudaGetSymbolAddress((void**)&xdbl,  g_xdbl);
    cudaGetSymbolAddress((void**)&xd_hi, g_xd_hi);
    cudaGetSymbolAddress((void**)&xd_lo, g_xd_lo);
    cudaGetSymbolAddress((void**)&part,  g_part);
    cudaGetSymbolAddress((void**)&dl,    g_dl);
    cudaGetSymbolAddress((void**)&y_hi,  g_y_hi);
    cudaGetSymbolAddress((void**)&y_lo,  g_y_lo);
    cudaGetSymbolAddress((void**)&wi_hi, g_wi_hi);
    cudaGetSymbolAddress((void**)&wi_lo, g_wi_lo);
    cudaGetSymbolAddress((void**)&xp_hi, g_xp_hi);
    cudaGetSymbolAddress((void**)&xp_lo, g_xp_lo);
    cudaGetSymbolAddress((void**)&dw_hi, g_dw_hi);
    cudaGetSymbolAddress((void**)&dw_lo, g_dw_lo);
    cudaGetSymbolAddress((void**)&wo_hi, g_wo_hi);
    cudaGetSymbolAddress((void**)&wo_lo, g_wo_lo);

    cudaFuncSetAttribute(gemm_f16x3<0,1>, cudaFuncAttributeMaxDynamicSharedMemorySize, G6_SMEM);
    cudaFuncSetAttribute(gemm_f16x3<0,XPROJ_SPLITK>, cudaFuncAttributeMaxDynamicSharedMemorySize, G6_SMEM);
    cudaFuncSetAttribute(gemm_f16x3<1,1>, cudaFuncAttributeMaxDynamicSharedMemorySize, G6_SMEM);
    cudaFuncSetAttribute(gemm_f16x3<2,1>, cudaFuncAttributeMaxDynamicSharedMemorySize, G6_SMEM);

    // 0. weight hi/lo splits (8 elems/thread)
    split_kernel<<<(2*D_INNER*D_MODEL/8 + 255)/256, 256>>>(W_in,  wi_hi, wi_lo, 2*D_INNER*D_MODEL);
    split_kernel<<<(XDBL_C*D_INNER/8   + 255)/256, 256>>>(x_proj, xp_hi, xp_lo, XDBL_C*D_INNER);
    split_kernel<<<(D_INNER*DT_RANK/8  + 255)/256, 256>>>(dt_w,   dw_hi, dw_lo, D_INNER*DT_RANK);
    split_kernel<<<(D_MODEL*D_INNER/8  + 255)/256, 256>>>(W_out,  wo_hi, wo_lo, D_MODEL*D_INNER);

    // 1. LayerNorm -> xn hi/lo
    ln_kernel<<<BL, 256>>>(x, ln_g, ln_b, xn_hi, xn_lo);

    // 2. xz = xn @ W_in^T   (4096 x 4096 x 1024)
    gemm_f16x3<0,1><<<dim3(2*D_INNER/128, BL/128), 256, G6_SMEM>>>(
        xn_hi, xn_lo, D_MODEL, wi_hi, wi_lo, D_MODEL,
        xz, 2*D_INNER, BL, 2*D_INNER, D_MODEL, nullptr, nullptr);

    // 3. causal depthwise conv + SiLU -> u (+ hi/lo), 4 ch/thread
    conv_silu_kernel<<<(BL*D_INNER/4 + 255)/256, 256>>>(xz, conv_w, conv_b, u, u_hi, u_lo);

    // 4. x_dbl = u @ x_proj^T  (4096 x 96 x 2048), split-K=4
    gemm_f16x3<0,XPROJ_SPLITK><<<dim3(1, BL/128, XPROJ_SPLITK), 256, G6_SMEM>>>(
        u_hi, u_lo, D_INNER, xp_hi, xp_lo, D_INNER,
        part, XDBL_C, BL, XDBL_C, D_INNER, nullptr, nullptr);
    xproj_reduce<<<(BL*XDBL_C/4 + 255)/256, 256>>>(part, xdbl, xd_hi, xd_lo);

    // 5. delta = softplus(dt_r @ dt_w^T + dt_b)  (4096 x 2048 x 64)
    gemm_f16x3<1,1><<<dim3(D_INNER/128, BL/128), 256, G6_SMEM>>>(
        xd_hi, xd_lo, XDBL_C, dw_hi, dw_lo, DT_RANK,
        dl, D_INNER, BL, D_INNER, DT_RANK, dt_b, nullptr);

    // 6. selective scan + fused gate -> y hi/lo
    scan_kernel<<<dim3(D_INNER/SC_DC, BSZ), SC_DC*D_STATE>>>(
        u, dl, xdbl, A_log, xz, D_prm, y_hi, y_lo);

    // 7. out = y @ W_out^T + x  (4096 x 1024 x 2048)
    gemm_f16x3<2,1><<<dim3(D_MODEL/128, BL/128), 256, G6_SMEM>>>(
        y_hi, y_lo, D_INNER, wo_hi, wo_lo, D_INNER,
        out, D_MODEL, BL, D_MODEL, D_INNER, nullptr, x);
}